// round 7
// baseline (speedup 1.0000x reference)
#include <cuda_runtime.h>
#include <math.h>
#include <stdint.h>

#define BATCH 256
#define SIGLEN 2048
#define L1P 1022
#define L2P 339
#define L3P 168
#define C1 128
#define C2 64
#define C3 64
#define FCIN 10752
#define EPS_BN 1e-5f

typedef unsigned long long ull;

// ---- scratch ----
__device__ float g_h1T[BATCH * L1P * C1];   // [b][pos][ic]
__device__ float g_h2T[BATCH * L2P * C2];   // [b][pos][oc]
__device__ float g_h3T[FCIN * BATCH];       // [feature][batch]
__device__ float g_w2T[5 * 64 * 128];       // [k][oc][ic]
__device__ float g_w3T[3 * 64 * 64];        // [k][oc][ic]
__device__ float g_part[256 * BATCH * 48];
__device__ float g_theta[BATCH * 5];

__device__ __forceinline__ void fma2(ull& d, ull a, ull b) {
    asm("fma.rn.f32x2 %0, %1, %2, %0;" : "+l"(d) : "l"(a), "l"(b));
}
__device__ __forceinline__ ull dup2(float v) {
    ull r; asm("mov.b64 %0, {%1, %1};" : "=l"(r) : "f"(v)); return r;
}
__device__ __forceinline__ float lo32(ull v) { return __uint_as_float((unsigned)v); }
__device__ __forceinline__ float hi32(ull v) { return __uint_as_float((unsigned)(v >> 32)); }

__device__ __forceinline__ void cpa16(void* dst, const void* src) {
    unsigned d = (unsigned)__cvta_generic_to_shared(dst);
    asm volatile("cp.async.cg.shared.global [%0], [%1], 16;" :: "r"(d), "l"(src));
}
__device__ __forceinline__ void cpa8(void* dst, const void* src) {
    unsigned d = (unsigned)__cvta_generic_to_shared(dst);
    asm volatile("cp.async.ca.shared.global [%0], [%1], 8;" :: "r"(d), "l"(src));
}
#define CP_COMMIT()  asm volatile("cp.async.commit_group;" ::: "memory")
#define CP_WAIT1()   asm volatile("cp.async.wait_group 1;" ::: "memory")
#define CP_WAIT0()   asm volatile("cp.async.wait_group 0;" ::: "memory")

// ============================================================
// Kernel 0: weight transposes
// ============================================================
__global__ void k_prep(const float* __restrict__ w2, const float* __restrict__ w3) {
    int i = blockIdx.x * blockDim.x + threadIdx.x;
    if (i < 5 * 64 * 128) {
        int k = i >> 13, oc = (i >> 7) & 63, ic = i & 127;
        g_w2T[i] = w2[oc * 640 + ic * 5 + k];
    }
    if (i < 3 * 64 * 64) {
        int k = i >> 12, oc = (i >> 6) & 63, ic = i & 63;
        g_w3T[i] = w3[oc * 192 + ic * 3 + k];
    }
}

// ============================================================
// Kernel 1: conv1 (3->128, k3) + BN + pool(3,2) + relu -> g_h1T[b][pos][ic]
// ============================================================
__global__ void __launch_bounds__(128) k_conv1(
        const float* __restrict__ x,
        const float* __restrict__ w,
        const float* __restrict__ bias,
        const float* __restrict__ bng,
        const float* __restrict__ bnb,
        const float* __restrict__ bnm,
        const float* __restrict__ bnv) {
    const int b  = blockIdx.y;
    const int p0 = blockIdx.x * 64;
    const int oc = threadIdx.x;
    __shared__ float xs[3][132];
    __shared__ float outS[64][128];

    const int t0 = 2 * p0;
    for (int idx = threadIdx.x; idx < 3 * 131; idx += 128) {
        int ch = idx / 131, j = idx % 131;
        int t = t0 + j;
        xs[ch][j] = (t < SIGLEN) ? x[(b * 3 + ch) * SIGLEN + t] : 0.f;
    }
    float wr[9];
#pragma unroll
    for (int j = 0; j < 9; ++j) wr[j] = w[oc * 9 + j];
    float scale = bng[oc] / sqrtf(bnv[oc] + EPS_BN);
    float shift = bnb[oc] + (bias[oc] - bnm[oc]) * scale;
    __syncthreads();

#pragma unroll 4
    for (int pl = 0; pl < 64; ++pl) {
        float c0 = 0.f, c1 = 0.f, c2 = 0.f;
        int base = 2 * pl;
#pragma unroll
        for (int ch = 0; ch < 3; ++ch)
#pragma unroll
            for (int k = 0; k < 3; ++k) {
                float wv = wr[ch * 3 + k];
                c0 = fmaf(wv, xs[ch][base + k], c0);
                c1 = fmaf(wv, xs[ch][base + 1 + k], c1);
                c2 = fmaf(wv, xs[ch][base + 2 + k], c2);
            }
        float y0 = fmaf(c0, scale, shift);
        float y1 = fmaf(c1, scale, shift);
        float y2 = fmaf(c2, scale, shift);
        outS[pl][oc] = fmaxf(fmaxf(fmaxf(y0, y1), y2), 0.f);
    }
    __syncthreads();
    for (int idx = threadIdx.x; idx < 64 * 128; idx += 128) {
        int pl = idx >> 7, col = idx & 127;
        int p = p0 + pl;
        if (p < L1P) g_h1T[(b * L1P + p) * C1 + col] = outS[pl][col];
    }
}

// ============================================================
// Kernel 2: conv2 (128->64, k5) + BN + pool(3,3) + relu  [HOT]
// Occupancy-first: 1 oc x 12 conv pos per thread (~75 regs, 3 blocks/SM).
// block 256 = 64 ocd x 4 gg. Tile 48 conv = 16 pooled. grid (22, 256).
// ic-pair f32x2, cp.async double-buffered, warp-broadcast x loads.
// ============================================================
__global__ void __launch_bounds__(256, 3) k_conv2(
        const float* __restrict__ bias,
        const float* __restrict__ bng,
        const float* __restrict__ bnb,
        const float* __restrict__ bnm,
        const float* __restrict__ bnv) {
    __shared__ float xs[2][52][16];
    __shared__ ull   ws[2][2560];     // [k*8+icp][oc]

    const int b    = blockIdx.y;
    const int tid  = threadIdx.x;
    const int ocd  = tid & 63;
    const int gg   = tid >> 6;        // 0..3
    const int tin0 = blockIdx.x * 48;

    const float* h1b = &g_h1T[(size_t)b * L1P * C1];

    ull acc[12];
#pragma unroll
    for (int m = 0; m < 12; ++m) acc[m] = 0ull;

    auto fill = [&](int c, int bi) {
        const int ic0 = c * 16;
        for (int idx = tid; idx < 52 * 4; idx += 256) {
            int j = idx >> 2, q = idx & 3;
            int t = tin0 + j;
            float* dst = &xs[bi][j][q * 4];
            if (t < L1P) cpa16(dst, &h1b[t * C1 + ic0 + q * 4]);
            else { dst[0] = 0.f; dst[1] = 0.f; dst[2] = 0.f; dst[3] = 0.f; }
        }
        for (int idx = tid; idx < 2560; idx += 256) {
            int oc = idx & 63, r = idx >> 6;      // r = k*8+icp
            cpa8(&ws[bi][idx], &g_w2T[((r >> 3) * 64 + oc) * 128 + ic0 + 2 * (r & 7)]);
        }
    };

    fill(0, 0); CP_COMMIT();
    for (int c = 0; c < 8; ++c) {
        if (c + 1 < 8) { fill(c + 1, (c + 1) & 1); CP_COMMIT(); CP_WAIT1(); }
        else           { CP_WAIT0(); }
        __syncthreads();
        const int bi = c & 1;
#pragma unroll 1
        for (int icp = 0; icp < 8; ++icp) {
            ull xd[16];
#pragma unroll
            for (int j = 0; j < 16; ++j)
                xd[j] = *(const ull*)&xs[bi][12 * gg + j][2 * icp];
            ull wv[5];
#pragma unroll
            for (int k = 0; k < 5; ++k)
                wv[k] = ws[bi][(k * 8 + icp) * 64 + ocd];
#pragma unroll
            for (int m = 0; m < 12; ++m)
#pragma unroll
                for (int k = 0; k < 5; ++k)
                    fma2(acc[m], wv[k], xd[m + k]);
        }
        __syncthreads();
    }

    // epilogue: 12 conv = 4 pooled, coalesced over oc lanes
    float scale = bng[ocd] / sqrtf(bnv[ocd] + EPS_BN);
    float shift = bnb[ocd] + (bias[ocd] - bnm[ocd]) * scale;
#pragma unroll
    for (int j = 0; j < 4; ++j) {
        int p = blockIdx.x * 16 + 4 * gg + j;
        if (p >= L2P) continue;
        ull a0 = acc[3 * j], a1 = acc[3 * j + 1], a2 = acc[3 * j + 2];
        float y0 = fmaf(lo32(a0) + hi32(a0), scale, shift);
        float y1 = fmaf(lo32(a1) + hi32(a1), scale, shift);
        float y2 = fmaf(lo32(a2) + hi32(a2), scale, shift);
        g_h2T[(b * L2P + p) * C2 + ocd] = fmaxf(fmaxf(fmaxf(y0, y1), y2), 0.f);
    }
}

// ============================================================
// Kernel 3: conv3 (64->64, k3) + BN + pool(3,2) + relu -> g_h3T[feat][b]
// 2 oc x 7 conv (3 pooled) per thread (~70 regs, 3 blocks/SM).
// block 256 = 32 ocd x 8 gg. Tile 24 pooled. grid (7, 256).
// ============================================================
__global__ void __launch_bounds__(256, 3) k_conv3(
        const float* __restrict__ bias,
        const float* __restrict__ bng,
        const float* __restrict__ bnb,
        const float* __restrict__ bnm,
        const float* __restrict__ bnv) {
    __shared__ float xs[2][51][16];
    __shared__ ull   ws[2][1536];     // [k*8+icp][oc]

    const int b    = blockIdx.y;
    const int tid  = threadIdx.x;
    const int ocd  = tid & 31;
    const int gg   = tid >> 5;        // 0..7
    const int tin0 = blockIdx.x * 48;

    ull acc0[7], acc1[7];
#pragma unroll
    for (int m = 0; m < 7; ++m) { acc0[m] = 0ull; acc1[m] = 0ull; }

    auto fill = [&](int c, int bi) {
        const int ic0 = c * 16;
        for (int idx = tid; idx < 51 * 4; idx += 256) {
            int j = idx >> 2, q = idx & 3;
            int t = tin0 + j;
            float* dst = &xs[bi][j][q * 4];
            if (t < L2P) cpa16(dst, &g_h2T[(b * L2P + t) * C2 + ic0 + q * 4]);
            else { dst[0] = 0.f; dst[1] = 0.f; dst[2] = 0.f; dst[3] = 0.f; }
        }
        for (int idx = tid; idx < 1536; idx += 256) {
            int oc = idx & 63, r = idx >> 6;     // r = k*8+icp
            cpa8(&ws[bi][idx], &g_w3T[((r >> 3) * 64 + oc) * 64 + ic0 + 2 * (r & 7)]);
        }
    };

    fill(0, 0); CP_COMMIT();
    for (int c = 0; c < 4; ++c) {
        if (c + 1 < 4) { fill(c + 1, (c + 1) & 1); CP_COMMIT(); CP_WAIT1(); }
        else           { CP_WAIT0(); }
        __syncthreads();
        const int bi = c & 1;
#pragma unroll 1
        for (int icp = 0; icp < 8; ++icp) {
            ull xd[9];
#pragma unroll
            for (int j = 0; j < 9; ++j)
                xd[j] = *(const ull*)&xs[bi][6 * gg + j][2 * icp];
            ull w0[3], w1[3];
#pragma unroll
            for (int k = 0; k < 3; ++k) {
                w0[k] = ws[bi][(k * 8 + icp) * 64 + ocd];
                w1[k] = ws[bi][(k * 8 + icp) * 64 + ocd + 32];
            }
#pragma unroll
            for (int m = 0; m < 7; ++m)
#pragma unroll
                for (int k = 0; k < 3; ++k) {
                    fma2(acc0[m], w0[k], xd[m + k]);
                    fma2(acc1[m], w1[k], xd[m + k]);
                }
        }
        __syncthreads();
    }

#pragma unroll
    for (int o2 = 0; o2 < 2; ++o2) {
        int oc = ocd + 32 * o2;
        float scale = bng[oc] / sqrtf(bnv[oc] + EPS_BN);
        float shift = bnb[oc] + (bias[oc] - bnm[oc]) * scale;
#pragma unroll
        for (int j = 0; j < 3; ++j) {
            int p = blockIdx.x * 24 + 3 * gg + j;
            if (p >= L3P) continue;
            ull a0 = o2 ? acc1[2 * j] : acc0[2 * j];
            ull a1 = o2 ? acc1[2 * j + 1] : acc0[2 * j + 1];
            ull a2 = o2 ? acc1[2 * j + 2] : acc0[2 * j + 2];
            float y0 = fmaf(lo32(a0) + hi32(a0), scale, shift);
            float y1 = fmaf(lo32(a1) + hi32(a1), scale, shift);
            float y2 = fmaf(lo32(a2) + hi32(a2), scale, shift);
            float y = fmaxf(fmaxf(fmaxf(y0, y1), y2), 0.f);
            g_h3T[(oc * L3P + p) * BATCH + b] = y;
        }
    }
}

// ============================================================
// Kernel 4a: fc1 split-K. 256 blocks x 42-wide K chunks.
// ============================================================
__global__ void __launch_bounds__(256) k_fcA(const float* __restrict__ fc1w) {
    const int chunk = blockIdx.x;
    const int r = threadIdx.x;
    __shared__ float wsS[42][48];

    for (int idx = r; idx < 42 * 48; idx += 256) {
        int o = idx / 42, k = idx % 42;
        wsS[k][o] = fc1w[o * FCIN + chunk * 42 + k];
    }
    __syncthreads();

    ull acc[24];
#pragma unroll
    for (int p = 0; p < 24; ++p) acc[p] = 0ull;

#pragma unroll 2
    for (int k = 0; k < 42; ++k) {
        float xv = g_h3T[(chunk * 42 + k) * BATCH + r];
        ull xd = dup2(xv);
#pragma unroll
        for (int p = 0; p < 24; ++p)
            fma2(acc[p], *(const ull*)&wsS[k][2 * p], xd);
    }
    float* outp = &g_part[(chunk * BATCH + r) * 48];
#pragma unroll
    for (int p = 0; p < 24; ++p) {
        outp[2 * p]     = lo32(acc[p]);
        outp[2 * p + 1] = hi32(acc[p]);
    }
}

// ============================================================
// Kernel 4b: reduce + fc2/fc3/fc4 + tanh
// ============================================================
__global__ void k_fcB(const float* __restrict__ fc1b,
                      const float* __restrict__ fc2w, const float* __restrict__ fc2b,
                      const float* __restrict__ fc3w, const float* __restrict__ fc3b,
                      const float* __restrict__ fc4w, const float* __restrict__ fc4b) {
    const int r = blockIdx.x;
    const int t = threadIdx.x;
    __shared__ float s1[48], s2[32], s3[16];

    if (t < 48) {
        float a = 0.f;
#pragma unroll 8
        for (int c = 0; c < 256; ++c)
            a += g_part[(c * BATCH + r) * 48 + t];
        s1[t] = fmaxf(a + fc1b[t], 0.f);
    }
    __syncthreads();
    if (t < 32) {
        float a2 = 0.f;
#pragma unroll
        for (int k = 0; k < 48; ++k) a2 = fmaf(s1[k], fc2w[t * 48 + k], a2);
        s2[t] = fmaxf(a2 + fc2b[t], 0.f);
    }
    __syncthreads();
    if (t < 16) {
        float a3 = 0.f;
#pragma unroll
        for (int k = 0; k < 32; ++k) a3 = fmaf(s2[k], fc3w[t * 32 + k], a3);
        s3[t] = fmaxf(a3 + fc3b[t], 0.f);
    }
    __syncthreads();
    if (t < 5) {
        float a4 = 0.f;
#pragma unroll
        for (int k = 0; k < 16; ++k) a4 = fmaf(s3[k], fc4w[t * 16 + k], a4);
        g_theta[r * 5 + t] = tanhf(a4 + fc4b[t]);
    }
}

// ============================================================
// Kernel 5: CPAB integrate + resample
// ============================================================
__global__ void k_warp(const float* __restrict__ x,
                       const float* __restrict__ basis,
                       float* __restrict__ out) {
    const int b   = blockIdx.x;
    const int tid = threadIdx.x;
    __shared__ float sa[6], sb[6];
    if (tid < 12) {
        float a = 0.f;
#pragma unroll
        for (int k = 0; k < 5; ++k)
            a = fmaf(g_theta[b * 5 + k], basis[tid * 5 + k], a);
        if (tid & 1) sb[tid >> 1] = a; else sa[tid >> 1] = a;
    }
    __syncthreads();
    float la[6], lb[6];
#pragma unroll
    for (int c = 0; c < 6; ++c) { la[c] = sa[c]; lb[c] = sb[c]; }
    const float INF = __int_as_float(0x7f800000);

    for (int r = 0; r < 8; ++r) {
        int i = tid + r * 256;
        float xv = (float)i / 2047.0f;
        float t = 1.0f;
#pragma unroll 1
        for (int it = 0; it < 7; ++it) {
            int c = (int)floorf(xv * 6.0f);
            c = c < 0 ? 0 : (c > 5 ? 5 : c);
            float a  = la[c];
            float bc = lb[c];
            float v  = fmaf(a, xv, bc);
            float xb = (v >= 0.f) ? (float)(c + 1) / 6.0f : (float)c / 6.0f;
            bool  big = fabsf(a) > 1e-8f;
            float a_s = big ? a : 1.0f;
            float boa = bc / a_s;
            float z   = xv + boa;
            float zb  = xb + boa;
            float zden  = (fabsf(z) > 1e-12f) ? z : 1e-12f;
            float ratio = zb / zden;
            float t_exp = logf(fmaxf(ratio, 1e-12f)) / a_s;
            float v_s   = (fabsf(v) > 1e-12f) ? v : 1.0f;
            float t_lin = (xb - xv) / v_s;
            float thit  = big ? t_exp : t_lin;
            bool valid = (fabsf(v) > 1e-12f) && (thit > 0.f) &&
                         ((big ? ratio : 1.0f) > 0.f);
            thit = valid ? thit : INF;
            float tau = fminf(t, thit);
            float x_new = big ? (z * expf(a * tau) - (z - xv))
                              : fmaf(bc, tau, xv);
            bool hit = (thit <= t);
            float nudge = (v >= 0.f) ? 1e-6f : -1e-6f;
            xv = hit ? (xb + nudge) : x_new;
            xv = fminf(fmaxf(xv, 0.f), 1.f);
            t = fmaxf(t - tau, 0.f);
        }
        float p = fminf(fmaxf(xv, 0.f), 1.f) * 2047.0f;
        int x0 = (int)floorf(p);
        x0 = x0 < 0 ? 0 : (x0 > 2046 ? 2046 : x0);
        float wgt = p - (float)x0;
#pragma unroll
        for (int ch = 0; ch < 3; ++ch) {
            float d0 = x[(b * 3 + ch) * SIGLEN + x0];
            float d1 = x[(b * 3 + ch) * SIGLEN + x0 + 1];
            out[(b * 3 + ch) * SIGLEN + i] = d0 * (1.0f - wgt) + d1 * wgt;
        }
    }
}

// ============================================================
extern "C" void kernel_launch(void* const* d_in, const int* in_sizes, int n_in,
                              void* d_out, int out_size) {
    const float* x     = (const float*)d_in[0];
    const float* c1w   = (const float*)d_in[1];
    const float* c1b   = (const float*)d_in[2];
    const float* bn1g  = (const float*)d_in[3];
    const float* bn1b  = (const float*)d_in[4];
    const float* bn1m  = (const float*)d_in[5];
    const float* bn1v  = (const float*)d_in[6];
    const float* c2w   = (const float*)d_in[7];
    const float* c2b   = (const float*)d_in[8];
    const float* bn2g  = (const float*)d_in[9];
    const float* bn2b  = (const float*)d_in[10];
    const float* bn2m  = (const float*)d_in[11];
    const float* bn2v  = (const float*)d_in[12];
    const float* c3w   = (const float*)d_in[13];
    const float* c3b   = (const float*)d_in[14];
    const float* bn3g  = (const float*)d_in[15];
    const float* bn3b  = (const float*)d_in[16];
    const float* bn3m  = (const float*)d_in[17];
    const float* bn3v  = (const float*)d_in[18];
    const float* fc1w  = (const float*)d_in[19];
    const float* fc1b  = (const float*)d_in[20];
    const float* fc2w  = (const float*)d_in[21];
    const float* fc2b  = (const float*)d_in[22];
    const float* fc3w  = (const float*)d_in[23];
    const float* fc3b  = (const float*)d_in[24];
    const float* fc4w  = (const float*)d_in[25];
    const float* fc4b  = (const float*)d_in[26];
    const float* basis = (const float*)d_in[27];
    float* out = (float*)d_out;

    k_prep<<<160, 256>>>(c2w, c3w);
    dim3 g1(16, BATCH);  k_conv1<<<g1, 128>>>(x, c1w, c1b, bn1g, bn1b, bn1m, bn1v);
    dim3 g2(22, BATCH);  k_conv2<<<g2, 256>>>(c2b, bn2g, bn2b, bn2m, bn2v);
    dim3 g3(7,  BATCH);  k_conv3<<<g3, 256>>>(c3b, bn3g, bn3b, bn3m, bn3v);
    k_fcA<<<256, 256>>>(fc1w);
    k_fcB<<<BATCH, 64>>>(fc1b, fc2w, fc2b, fc3w, fc3b, fc4w, fc4b);
    k_warp<<<BATCH, 256>>>(x, basis, out);
}

// round 8
// speedup vs baseline: 1.2034x; 1.2034x over previous
#include <cuda_runtime.h>
#include <math.h>
#include <stdint.h>

#define BATCH 256
#define SIGLEN 2048
#define L1P 1022
#define L2P 339
#define L3P 168
#define C1 128
#define C2 64
#define C3 64
#define FCIN 10752
#define EPS_BN 1e-5f

typedef unsigned long long ull;

// ---- scratch ----
__device__ float g_h1T[BATCH * L1P * C1];   // [b][pos][ic]
__device__ float g_h2T[BATCH * L2P * C2];   // [b][pos][oc]
__device__ float g_h3T[FCIN * BATCH];       // [feature][batch]
__device__ float g_w2T[5 * 64 * 128];       // [k][oc][ic]
__device__ float g_w3T[3 * 64 * 64];        // [k][oc][ic]
__device__ float g_part[256 * BATCH * 48];
__device__ float g_theta[BATCH * 5];

__device__ __forceinline__ void fma2(ull& d, ull a, ull b) {
    asm("fma.rn.f32x2 %0, %1, %2, %0;" : "+l"(d) : "l"(a), "l"(b));
}
__device__ __forceinline__ ull dup2(float v) {
    ull r; asm("mov.b64 %0, {%1, %1};" : "=l"(r) : "f"(v)); return r;
}
__device__ __forceinline__ float lo32(ull v) { return __uint_as_float((unsigned)v); }
__device__ __forceinline__ float hi32(ull v) { return __uint_as_float((unsigned)(v >> 32)); }

__device__ __forceinline__ void cpa16(void* dst, const void* src) {
    unsigned d = (unsigned)__cvta_generic_to_shared(dst);
    asm volatile("cp.async.cg.shared.global [%0], [%1], 16;" :: "r"(d), "l"(src));
}
__device__ __forceinline__ void cpa8(void* dst, const void* src) {
    unsigned d = (unsigned)__cvta_generic_to_shared(dst);
    asm volatile("cp.async.ca.shared.global [%0], [%1], 8;" :: "r"(d), "l"(src));
}
#define CP_COMMIT()  asm volatile("cp.async.commit_group;" ::: "memory")
#define CP_WAIT1()   asm volatile("cp.async.wait_group 1;" ::: "memory")
#define CP_WAIT0()   asm volatile("cp.async.wait_group 0;" ::: "memory")

// ============================================================
// Kernel 0: weight transposes
// ============================================================
__global__ void k_prep(const float* __restrict__ w2, const float* __restrict__ w3) {
    int i = blockIdx.x * blockDim.x + threadIdx.x;
    if (i < 5 * 64 * 128) {
        int k = i >> 13, oc = (i >> 7) & 63, ic = i & 127;
        g_w2T[i] = w2[oc * 640 + ic * 5 + k];
    }
    if (i < 3 * 64 * 64) {
        int k = i >> 12, oc = (i >> 6) & 63, ic = i & 63;
        g_w3T[i] = w3[oc * 192 + ic * 3 + k];
    }
}

// ============================================================
// Kernel 1: conv1 (3->128, k3) + BN + pool(3,2) + relu -> g_h1T[b][pos][ic]
// ============================================================
__global__ void __launch_bounds__(128) k_conv1(
        const float* __restrict__ x,
        const float* __restrict__ w,
        const float* __restrict__ bias,
        const float* __restrict__ bng,
        const float* __restrict__ bnb,
        const float* __restrict__ bnm,
        const float* __restrict__ bnv) {
    const int b  = blockIdx.y;
    const int p0 = blockIdx.x * 64;
    const int oc = threadIdx.x;
    __shared__ float xs[3][132];
    __shared__ float outS[64][128];

    const int t0 = 2 * p0;
    for (int idx = threadIdx.x; idx < 3 * 131; idx += 128) {
        int ch = idx / 131, j = idx % 131;
        int t = t0 + j;
        xs[ch][j] = (t < SIGLEN) ? x[(b * 3 + ch) * SIGLEN + t] : 0.f;
    }
    float wr[9];
#pragma unroll
    for (int j = 0; j < 9; ++j) wr[j] = w[oc * 9 + j];
    float scale = bng[oc] / sqrtf(bnv[oc] + EPS_BN);
    float shift = bnb[oc] + (bias[oc] - bnm[oc]) * scale;
    __syncthreads();

#pragma unroll 4
    for (int pl = 0; pl < 64; ++pl) {
        float c0 = 0.f, c1 = 0.f, c2 = 0.f;
        int base = 2 * pl;
#pragma unroll
        for (int ch = 0; ch < 3; ++ch)
#pragma unroll
            for (int k = 0; k < 3; ++k) {
                float wv = wr[ch * 3 + k];
                c0 = fmaf(wv, xs[ch][base + k], c0);
                c1 = fmaf(wv, xs[ch][base + 1 + k], c1);
                c2 = fmaf(wv, xs[ch][base + 2 + k], c2);
            }
        float y0 = fmaf(c0, scale, shift);
        float y1 = fmaf(c1, scale, shift);
        float y2 = fmaf(c2, scale, shift);
        outS[pl][oc] = fmaxf(fmaxf(fmaxf(y0, y1), y2), 0.f);
    }
    __syncthreads();
    for (int idx = threadIdx.x; idx < 64 * 128; idx += 128) {
        int pl = idx >> 7, col = idx & 127;
        int p = p0 + pl;
        if (p < L1P) g_h1T[(b * L1P + p) * C1 + col] = outS[pl][col];
    }
}

// ============================================================
// Kernel 2: conv2 (128->64, k5) + BN + pool(3,3) + relu  [HOT]
// ic-pair f32x2, reg-blocked: 15 conv pos (5 pooled) x 2 oc per thread
// -> 150 fma2 / 29 LDS.64 per icp. block 256 = 32 ocd x 8 gg.
// Tile 120 conv = 40 pooled. grid (9, 256). cp.async double-buffered.
// ============================================================
#define CV2_SMEM (2 * (124 * 16 * 4) + 2 * (2560 * 8))   // 56832 B

__global__ void __launch_bounds__(256, 2) k_conv2(
        const float* __restrict__ bias,
        const float* __restrict__ bng,
        const float* __restrict__ bnb,
        const float* __restrict__ bnm,
        const float* __restrict__ bnv) {
    extern __shared__ char smem[];
    float (*xs0)[16] = (float(*)[16])(smem);
    float (*xs1)[16] = (float(*)[16])(smem + 7936);
    ull* ws0 = (ull*)(smem + 15872);
    ull* ws1 = (ull*)(smem + 36352);

    const int b   = blockIdx.y;
    const int ct0 = blockIdx.x * 120;     // first conv position of tile
    const int tid = threadIdx.x;
    const int ocd = tid & 31;
    const int gg  = tid >> 5;             // 0..7, 15 conv pos each

    const float* h1b = &g_h1T[(size_t)b * L1P * C1];

    ull acc0[15], acc1[15];
#pragma unroll
    for (int m = 0; m < 15; ++m) { acc0[m] = 0ull; acc1[m] = 0ull; }

    auto fill = [&](int c, int bi) {
        float (*xsb)[16] = bi ? xs1 : xs0;
        ull* wsb = bi ? ws1 : ws0;
        const int ic0 = c * 16;
        for (int idx = tid; idx < 124 * 4; idx += 256) {
            int j = idx >> 2, q = idx & 3;
            int t = ct0 + j;
            float* dst = &xsb[j][q * 4];
            if (t < L1P) cpa16(dst, &h1b[t * C1 + ic0 + q * 4]);
            else { dst[0] = 0.f; dst[1] = 0.f; dst[2] = 0.f; dst[3] = 0.f; }
        }
        for (int idx = tid; idx < 2560; idx += 256) {
            int oc = idx & 63, r = idx >> 6;      // r = k*8+icp
            cpa8(&wsb[idx], &g_w2T[((r >> 3) * 64 + oc) * 128 + ic0 + 2 * (r & 7)]);
        }
    };

    fill(0, 0); CP_COMMIT();
    for (int c = 0; c < 8; ++c) {
        if (c + 1 < 8) { fill(c + 1, (c + 1) & 1); CP_COMMIT(); CP_WAIT1(); }
        else           { CP_WAIT0(); }
        __syncthreads();
        float (*xsb)[16] = (c & 1) ? xs1 : xs0;
        ull* wsb = (c & 1) ? ws1 : ws0;
#pragma unroll 1
        for (int icp = 0; icp < 8; ++icp) {
            ull xd[19];
#pragma unroll
            for (int j = 0; j < 19; ++j)
                xd[j] = *(const ull*)&xsb[15 * gg + j][2 * icp];
            ull w0[5], w1[5];
#pragma unroll
            for (int k = 0; k < 5; ++k) {
                w0[k] = wsb[(k * 8 + icp) * 64 + ocd];
                w1[k] = wsb[(k * 8 + icp) * 64 + ocd + 32];
            }
#pragma unroll
            for (int m = 0; m < 15; ++m)
#pragma unroll
                for (int k = 0; k < 5; ++k) {
                    fma2(acc0[m], w0[k], xd[m + k]);
                    fma2(acc1[m], w1[k], xd[m + k]);
                }
        }
        __syncthreads();
    }

    // epilogue: 15 conv = 5 pooled per thread, coalesced over oc lanes
#pragma unroll
    for (int o2 = 0; o2 < 2; ++o2) {
        int oc = ocd + 32 * o2;
        float scale = bng[oc] / sqrtf(bnv[oc] + EPS_BN);
        float shift = bnb[oc] + (bias[oc] - bnm[oc]) * scale;
#pragma unroll
        for (int j = 0; j < 5; ++j) {
            int p = blockIdx.x * 40 + 5 * gg + j;
            if (p >= L2P) continue;
            ull a0 = o2 ? acc1[3 * j] : acc0[3 * j];
            ull a1 = o2 ? acc1[3 * j + 1] : acc0[3 * j + 1];
            ull a2 = o2 ? acc1[3 * j + 2] : acc0[3 * j + 2];
            float y0 = fmaf(lo32(a0) + hi32(a0), scale, shift);
            float y1 = fmaf(lo32(a1) + hi32(a1), scale, shift);
            float y2 = fmaf(lo32(a2) + hi32(a2), scale, shift);
            g_h2T[(b * L2P + p) * C2 + oc] = fmaxf(fmaxf(fmaxf(y0, y1), y2), 0.f);
        }
    }
}

// ============================================================
// Kernel 3: conv3 (64->64, k3) + BN + pool(3,2) + relu -> g_h3T[feat][b]
// (R6 best version) 16 ocd x 16 gg; 4 oc x 7 conv (3 pooled) per thread.
// Tile 96 conv = 48 pooled. grid (4, 256). Padded xs rows (20 floats).
// ============================================================
__global__ void __launch_bounds__(256, 2) k_conv3(
        const float* __restrict__ bias,
        const float* __restrict__ bng,
        const float* __restrict__ bnb,
        const float* __restrict__ bnm,
        const float* __restrict__ bnv) {
    __shared__ float xs[2][99][20];
    __shared__ ull   ws[2][1536];     // [k*8+icp][oc]

    const int b   = blockIdx.y;
    const int ct0 = blockIdx.x * 96;
    const int tid = threadIdx.x;
    const int ocd = tid & 15;
    const int gg  = tid >> 4;

    ull acc[4][7];
#pragma unroll
    for (int q = 0; q < 4; ++q)
#pragma unroll
        for (int m = 0; m < 7; ++m) acc[q][m] = 0ull;

    auto fill = [&](int c, int bi) {
        const int ic0 = c * 16;
        for (int idx = tid; idx < 99 * 4; idx += 256) {
            int j = idx >> 2, q = idx & 3;
            int t = ct0 + j;
            float* dst = &xs[bi][j][q * 4];
            if (t < L2P) cpa16(dst, &g_h2T[(b * L2P + t) * C2 + ic0 + q * 4]);
            else { dst[0] = 0.f; dst[1] = 0.f; dst[2] = 0.f; dst[3] = 0.f; }
        }
        for (int idx = tid; idx < 1536; idx += 256) {
            int oc = idx & 63, r = idx >> 6;     // r = k*8+icp
            cpa8(&ws[bi][idx], &g_w3T[((r >> 3) * 64 + oc) * 64 + ic0 + 2 * (r & 7)]);
        }
    };

    fill(0, 0); CP_COMMIT();
    for (int c = 0; c < 4; ++c) {
        if (c + 1 < 4) { fill(c + 1, (c + 1) & 1); CP_COMMIT(); CP_WAIT1(); }
        else           { CP_WAIT0(); }
        __syncthreads();
        const int bi = c & 1;
#pragma unroll 1
        for (int icp = 0; icp < 8; ++icp) {
            ull xd[9];
#pragma unroll
            for (int j = 0; j < 9; ++j)
                xd[j] = *(const ull*)&xs[bi][6 * gg + j][2 * icp];
            ull wv[4][3];
#pragma unroll
            for (int k = 0; k < 3; ++k) {
#pragma unroll
                for (int q = 0; q < 4; ++q)
                    wv[q][k] = ws[bi][(k * 8 + icp) * 64 + ocd + 16 * q];
            }
#pragma unroll
            for (int m = 0; m < 7; ++m)
#pragma unroll
                for (int k = 0; k < 3; ++k)
#pragma unroll
                    for (int q = 0; q < 4; ++q)
                        fma2(acc[q][m], wv[q][k], xd[m + k]);
        }
        __syncthreads();
    }

#pragma unroll
    for (int q = 0; q < 4; ++q) {
        int oc = ocd + 16 * q;
        float scale = bng[oc] / sqrtf(bnv[oc] + EPS_BN);
        float shift = bnb[oc] + (bias[oc] - bnm[oc]) * scale;
#pragma unroll
        for (int j = 0; j < 3; ++j) {
            int p = blockIdx.x * 48 + 3 * gg + j;
            if (p >= L3P) continue;
            ull a0 = acc[q][2 * j], a1 = acc[q][2 * j + 1], a2 = acc[q][2 * j + 2];
            float y0 = fmaf(lo32(a0) + hi32(a0), scale, shift);
            float y1 = fmaf(lo32(a1) + hi32(a1), scale, shift);
            float y2 = fmaf(lo32(a2) + hi32(a2), scale, shift);
            float y = fmaxf(fmaxf(fmaxf(y0, y1), y2), 0.f);
            g_h3T[(oc * L3P + p) * BATCH + b] = y;
        }
    }
}

// ============================================================
// Kernel 4a: fc1 split-K. 256 blocks x 42-wide K chunks.
// ============================================================
__global__ void __launch_bounds__(256) k_fcA(const float* __restrict__ fc1w) {
    const int chunk = blockIdx.x;
    const int r = threadIdx.x;
    __shared__ float wsS[42][48];

    for (int idx = r; idx < 42 * 48; idx += 256) {
        int o = idx / 42, k = idx % 42;
        wsS[k][o] = fc1w[o * FCIN + chunk * 42 + k];
    }
    __syncthreads();

    ull acc[24];
#pragma unroll
    for (int p = 0; p < 24; ++p) acc[p] = 0ull;

#pragma unroll 2
    for (int k = 0; k < 42; ++k) {
        float xv = g_h3T[(chunk * 42 + k) * BATCH + r];
        ull xd = dup2(xv);
#pragma unroll
        for (int p = 0; p < 24; ++p)
            fma2(acc[p], *(const ull*)&wsS[k][2 * p], xd);
    }
    float* outp = &g_part[(chunk * BATCH + r) * 48];
#pragma unroll
    for (int p = 0; p < 24; ++p) {
        outp[2 * p]     = lo32(acc[p]);
        outp[2 * p + 1] = hi32(acc[p]);
    }
}

// ============================================================
// Kernel 4b: reduce + fc2/fc3/fc4 + tanh
// ============================================================
__global__ void k_fcB(const float* __restrict__ fc1b,
                      const float* __restrict__ fc2w, const float* __restrict__ fc2b,
                      const float* __restrict__ fc3w, const float* __restrict__ fc3b,
                      const float* __restrict__ fc4w, const float* __restrict__ fc4b) {
    const int r = blockIdx.x;
    const int t = threadIdx.x;
    __shared__ float s1[48], s2[32], s3[16];

    if (t < 48) {
        float a = 0.f;
#pragma unroll 8
        for (int c = 0; c < 256; ++c)
            a += g_part[(c * BATCH + r) * 48 + t];
        s1[t] = fmaxf(a + fc1b[t], 0.f);
    }
    __syncthreads();
    if (t < 32) {
        float a2 = 0.f;
#pragma unroll
        for (int k = 0; k < 48; ++k) a2 = fmaf(s1[k], fc2w[t * 48 + k], a2);
        s2[t] = fmaxf(a2 + fc2b[t], 0.f);
    }
    __syncthreads();
    if (t < 16) {
        float a3 = 0.f;
#pragma unroll
        for (int k = 0; k < 32; ++k) a3 = fmaf(s2[k], fc3w[t * 32 + k], a3);
        s3[t] = fmaxf(a3 + fc3b[t], 0.f);
    }
    __syncthreads();
    if (t < 5) {
        float a4 = 0.f;
#pragma unroll
        for (int k = 0; k < 16; ++k) a4 = fmaf(s3[k], fc4w[t * 16 + k], a4);
        g_theta[r * 5 + t] = tanhf(a4 + fc4b[t]);
    }
}

// ============================================================
// Kernel 5: CPAB integrate + resample
// ============================================================
__global__ void k_warp(const float* __restrict__ x,
                       const float* __restrict__ basis,
                       float* __restrict__ out) {
    const int b   = blockIdx.x;
    const int tid = threadIdx.x;
    __shared__ float sa[6], sb[6];
    if (tid < 12) {
        float a = 0.f;
#pragma unroll
        for (int k = 0; k < 5; ++k)
            a = fmaf(g_theta[b * 5 + k], basis[tid * 5 + k], a);
        if (tid & 1) sb[tid >> 1] = a; else sa[tid >> 1] = a;
    }
    __syncthreads();
    float la[6], lb[6];
#pragma unroll
    for (int c = 0; c < 6; ++c) { la[c] = sa[c]; lb[c] = sb[c]; }
    const float INF = __int_as_float(0x7f800000);

    for (int r = 0; r < 8; ++r) {
        int i = tid + r * 256;
        float xv = (float)i / 2047.0f;
        float t = 1.0f;
#pragma unroll 1
        for (int it = 0; it < 7; ++it) {
            int c = (int)floorf(xv * 6.0f);
            c = c < 0 ? 0 : (c > 5 ? 5 : c);
            float a  = la[c];
            float bc = lb[c];
            float v  = fmaf(a, xv, bc);
            float xb = (v >= 0.f) ? (float)(c + 1) / 6.0f : (float)c / 6.0f;
            bool  big = fabsf(a) > 1e-8f;
            float a_s = big ? a : 1.0f;
            float boa = bc / a_s;
            float z   = xv + boa;
            float zb  = xb + boa;
            float zden  = (fabsf(z) > 1e-12f) ? z : 1e-12f;
            float ratio = zb / zden;
            float t_exp = logf(fmaxf(ratio, 1e-12f)) / a_s;
            float v_s   = (fabsf(v) > 1e-12f) ? v : 1.0f;
            float t_lin = (xb - xv) / v_s;
            float thit  = big ? t_exp : t_lin;
            bool valid = (fabsf(v) > 1e-12f) && (thit > 0.f) &&
                         ((big ? ratio : 1.0f) > 0.f);
            thit = valid ? thit : INF;
            float tau = fminf(t, thit);
            float x_new = big ? (z * expf(a * tau) - (z - xv))
                              : fmaf(bc, tau, xv);
            bool hit = (thit <= t);
            float nudge = (v >= 0.f) ? 1e-6f : -1e-6f;
            xv = hit ? (xb + nudge) : x_new;
            xv = fminf(fmaxf(xv, 0.f), 1.f);
            t = fmaxf(t - tau, 0.f);
        }
        float p = fminf(fmaxf(xv, 0.f), 1.f) * 2047.0f;
        int x0 = (int)floorf(p);
        x0 = x0 < 0 ? 0 : (x0 > 2046 ? 2046 : x0);
        float wgt = p - (float)x0;
#pragma unroll
        for (int ch = 0; ch < 3; ++ch) {
            float d0 = x[(b * 3 + ch) * SIGLEN + x0];
            float d1 = x[(b * 3 + ch) * SIGLEN + x0 + 1];
            out[(b * 3 + ch) * SIGLEN + i] = d0 * (1.0f - wgt) + d1 * wgt;
        }
    }
}

// ============================================================
extern "C" void kernel_launch(void* const* d_in, const int* in_sizes, int n_in,
                              void* d_out, int out_size) {
    const float* x     = (const float*)d_in[0];
    const float* c1w   = (const float*)d_in[1];
    const float* c1b   = (const float*)d_in[2];
    const float* bn1g  = (const float*)d_in[3];
    const float* bn1b  = (const float*)d_in[4];
    const float* bn1m  = (const float*)d_in[5];
    const float* bn1v  = (const float*)d_in[6];
    const float* c2w   = (const float*)d_in[7];
    const float* c2b   = (const float*)d_in[8];
    const float* bn2g  = (const float*)d_in[9];
    const float* bn2b  = (const float*)d_in[10];
    const float* bn2m  = (const float*)d_in[11];
    const float* bn2v  = (const float*)d_in[12];
    const float* c3w   = (const float*)d_in[13];
    const float* c3b   = (const float*)d_in[14];
    const float* bn3g  = (const float*)d_in[15];
    const float* bn3b  = (const float*)d_in[16];
    const float* bn3m  = (const float*)d_in[17];
    const float* bn3v  = (const float*)d_in[18];
    const float* fc1w  = (const float*)d_in[19];
    const float* fc1b  = (const float*)d_in[20];
    const float* fc2w  = (const float*)d_in[21];
    const float* fc2b  = (const float*)d_in[22];
    const float* fc3w  = (const float*)d_in[23];
    const float* fc3b  = (const float*)d_in[24];
    const float* fc4w  = (const float*)d_in[25];
    const float* fc4b  = (const float*)d_in[26];
    const float* basis = (const float*)d_in[27];
    float* out = (float*)d_out;

    static int attr_done = 0;
    if (!attr_done) {
        cudaFuncSetAttribute(k_conv2,
                             cudaFuncAttributeMaxDynamicSharedMemorySize, CV2_SMEM);
        attr_done = 1;
    }

    k_prep<<<160, 256>>>(c2w, c3w);
    dim3 g1(16, BATCH);  k_conv1<<<g1, 128>>>(x, c1w, c1b, bn1g, bn1b, bn1m, bn1v);
    dim3 g2(9,  BATCH);  k_conv2<<<g2, 256, CV2_SMEM>>>(c2b, bn2g, bn2b, bn2m, bn2v);
    dim3 g3(4,  BATCH);  k_conv3<<<g3, 256>>>(c3b, bn3g, bn3b, bn3m, bn3v);
    k_fcA<<<256, 256>>>(fc1w);
    k_fcB<<<BATCH, 64>>>(fc1b, fc2w, fc2b, fc3w, fc3b, fc4w, fc4b);
    k_warp<<<BATCH, 256>>>(x, basis, out);
}

// round 9
// speedup vs baseline: 1.3820x; 1.1483x over previous
#include <cuda_runtime.h>
#include <math.h>
#include <stdint.h>

#define BATCH 256
#define SIGLEN 2048
#define L1P 1022
#define L2P 339
#define L3P 168
#define C1 128
#define C2 64
#define C3 64
#define FCIN 10752
#define EPS_BN 1e-5f

typedef unsigned long long ull;

// ---- scratch ----
__device__ float g_h1T[BATCH * L1P * C1];   // [b][pos][ic]
__device__ float g_h2T[BATCH * L2P * C2];   // [b][pos][oc]
__device__ float g_h3T[FCIN * BATCH];       // [feature][batch]
__device__ float g_w2T[5 * 64 * 128];       // [k][oc][ic]
__device__ float g_w3T[3 * 64 * 64];        // [k][oc][ic]
__device__ float g_part[256 * BATCH * 48];
__device__ float g_theta[BATCH * 5];

__device__ __forceinline__ void fma2(ull& d, ull a, ull b) {
    asm("fma.rn.f32x2 %0, %1, %2, %0;" : "+l"(d) : "l"(a), "l"(b));
}
__device__ __forceinline__ ull dup2(float v) {
    ull r; asm("mov.b64 %0, {%1, %1};" : "=l"(r) : "f"(v)); return r;
}
__device__ __forceinline__ float lo32(ull v) { return __uint_as_float((unsigned)v); }
__device__ __forceinline__ float hi32(ull v) { return __uint_as_float((unsigned)(v >> 32)); }

__device__ __forceinline__ void cpa16(void* dst, const void* src) {
    unsigned d = (unsigned)__cvta_generic_to_shared(dst);
    asm volatile("cp.async.cg.shared.global [%0], [%1], 16;" :: "r"(d), "l"(src));
}
__device__ __forceinline__ void cpa8(void* dst, const void* src) {
    unsigned d = (unsigned)__cvta_generic_to_shared(dst);
    asm volatile("cp.async.ca.shared.global [%0], [%1], 8;" :: "r"(d), "l"(src));
}
#define CP_COMMIT()  asm volatile("cp.async.commit_group;" ::: "memory")
#define CP_WAIT1()   asm volatile("cp.async.wait_group 1;" ::: "memory")
#define CP_WAIT0()   asm volatile("cp.async.wait_group 0;" ::: "memory")

__device__ __forceinline__ float f2tf_f(float v) {
    unsigned r; asm("cvt.rna.tf32.f32 %0, %1;" : "=r"(r) : "f"(v));
    return __uint_as_float(r);
}
__device__ __forceinline__ void mma_tf32(float* d,
        unsigned a0, unsigned a1, unsigned a2, unsigned a3,
        unsigned b0, unsigned b1) {
    asm("mma.sync.aligned.m16n8k8.row.col.f32.tf32.tf32.f32 "
        "{%0,%1,%2,%3}, {%4,%5,%6,%7}, {%8,%9}, {%0,%1,%2,%3};"
        : "+f"(d[0]), "+f"(d[1]), "+f"(d[2]), "+f"(d[3])
        : "r"(a0), "r"(a1), "r"(a2), "r"(a3), "r"(b0), "r"(b1));
}

// ============================================================
// Kernel 0: weight transposes
// ============================================================
__global__ void k_prep(const float* __restrict__ w2, const float* __restrict__ w3) {
    int i = blockIdx.x * blockDim.x + threadIdx.x;
    if (i < 5 * 64 * 128) {
        int k = i >> 13, oc = (i >> 7) & 63, ic = i & 127;
        g_w2T[i] = w2[oc * 640 + ic * 5 + k];
    }
    if (i < 3 * 64 * 64) {
        int k = i >> 12, oc = (i >> 6) & 63, ic = i & 63;
        g_w3T[i] = w3[oc * 192 + ic * 3 + k];
    }
}

// ============================================================
// Kernel 1: conv1 (3->128, k3) + BN + pool(3,2) + relu -> g_h1T[b][pos][ic]
// ============================================================
__global__ void __launch_bounds__(128) k_conv1(
        const float* __restrict__ x,
        const float* __restrict__ w,
        const float* __restrict__ bias,
        const float* __restrict__ bng,
        const float* __restrict__ bnb,
        const float* __restrict__ bnm,
        const float* __restrict__ bnv) {
    const int b  = blockIdx.y;
    const int p0 = blockIdx.x * 64;
    const int oc = threadIdx.x;
    __shared__ float xs[3][132];
    __shared__ float outS[64][128];

    const int t0 = 2 * p0;
    for (int idx = threadIdx.x; idx < 3 * 131; idx += 128) {
        int ch = idx / 131, j = idx % 131;
        int t = t0 + j;
        xs[ch][j] = (t < SIGLEN) ? x[(b * 3 + ch) * SIGLEN + t] : 0.f;
    }
    float wr[9];
#pragma unroll
    for (int j = 0; j < 9; ++j) wr[j] = w[oc * 9 + j];
    float scale = bng[oc] / sqrtf(bnv[oc] + EPS_BN);
    float shift = bnb[oc] + (bias[oc] - bnm[oc]) * scale;
    __syncthreads();

#pragma unroll 4
    for (int pl = 0; pl < 64; ++pl) {
        float c0 = 0.f, c1 = 0.f, c2 = 0.f;
        int base = 2 * pl;
#pragma unroll
        for (int ch = 0; ch < 3; ++ch)
#pragma unroll
            for (int k = 0; k < 3; ++k) {
                float wv = wr[ch * 3 + k];
                c0 = fmaf(wv, xs[ch][base + k], c0);
                c1 = fmaf(wv, xs[ch][base + 1 + k], c1);
                c2 = fmaf(wv, xs[ch][base + 2 + k], c2);
            }
        float y0 = fmaf(c0, scale, shift);
        float y1 = fmaf(c1, scale, shift);
        float y2 = fmaf(c2, scale, shift);
        outS[pl][oc] = fmaxf(fmaxf(fmaxf(y0, y1), y2), 0.f);
    }
    __syncthreads();
    for (int idx = threadIdx.x; idx < 64 * 128; idx += 128) {
        int pl = idx >> 7, col = idx & 127;
        int p = p0 + pl;
        if (p < L1P) g_h1T[(b * L1P + p) * C1 + col] = outS[pl][col];
    }
}

// ============================================================
// Kernel 2: conv2 via mma.sync tf32 3x-split implicit GEMM  [HOT]
// D[128 pos][64 oc] = sum_k X_k[pos][128 ic] W_k[oc][128 ic]
// Block: 256 thr = 8 warps (4 M-groups x 2 N-groups), warp tile m32 n32.
// X staged once (hi/lo, stride-132 rows), W per-k. grid (9, 256).
// ============================================================
#define CV2_SMEM (51872 * 4)   // 207,488 B

__global__ void __launch_bounds__(256, 1) k_conv2mma(
        const float* __restrict__ bias,
        const float* __restrict__ bng,
        const float* __restrict__ bnb,
        const float* __restrict__ bnm,
        const float* __restrict__ bnv) {
    extern __shared__ float sm[];
    float* xh  = sm;               // [132][132]
    float* xl  = sm + 17424;
    float* wh  = sm + 34848;       // [64][132]
    float* wl  = sm + 43296;
    float* scS = sm + 51744;       // [64]
    float* shS = sm + 51808;       // [64]

    const int b    = blockIdx.y;
    const int bx   = blockIdx.x;
    const int ct0  = bx * 126;
    const int tid  = threadIdx.x;
    const int lane = tid & 31;
    const int wid  = tid >> 5;
    const int mw   = wid & 3;      // M group (32 rows)
    const int nw   = wid >> 2;     // N group (32 cols)

    if (tid < 64) {
        float sc = bng[tid] * rsqrtf(bnv[tid] + EPS_BN);
        scS[tid] = sc;
        shS[tid] = bnb[tid] + (bias[tid] - bnm[tid]) * sc;
    }

    // ---- stage X (132 rows x 128 ic), hi/lo tf32 split ----
    const float* h1b = &g_h1T[(size_t)b * L1P * C1];
    for (int idx = tid; idx < 132 * 32; idx += 256) {
        int j = idx >> 5, icq = idx & 31;
        int t = ct0 + j;
        float4 v = (t < L1P) ? ((const float4*)(h1b + (size_t)t * C1))[icq]
                             : make_float4(0.f, 0.f, 0.f, 0.f);
        float4 hv, lv;
        hv.x = f2tf_f(v.x); lv.x = f2tf_f(v.x - hv.x);
        hv.y = f2tf_f(v.y); lv.y = f2tf_f(v.y - hv.y);
        hv.z = f2tf_f(v.z); lv.z = f2tf_f(v.z - hv.z);
        hv.w = f2tf_f(v.w); lv.w = f2tf_f(v.w - hv.w);
        *(float4*)(xh + j * 132 + icq * 4) = hv;
        *(float4*)(xl + j * 132 + icq * 4) = lv;
    }

    auto fillW = [&](int k) {
        for (int idx = tid; idx < 64 * 32; idx += 256) {
            int oc = idx >> 5, icq = idx & 31;
            float4 v = ((const float4*)(g_w2T + (k * 64 + oc) * 128))[icq];
            float4 hv, lv;
            hv.x = f2tf_f(v.x); lv.x = f2tf_f(v.x - hv.x);
            hv.y = f2tf_f(v.y); lv.y = f2tf_f(v.y - hv.y);
            hv.z = f2tf_f(v.z); lv.z = f2tf_f(v.z - hv.z);
            hv.w = f2tf_f(v.w); lv.w = f2tf_f(v.w - hv.w);
            *(float4*)(wh + oc * 132 + icq * 4) = hv;
            *(float4*)(wl + oc * 132 + icq * 4) = lv;
        }
    };
    fillW(0);
    __syncthreads();

    float c[2][4][4];
#pragma unroll
    for (int ms = 0; ms < 2; ++ms)
#pragma unroll
        for (int j = 0; j < 4; ++j)
#pragma unroll
            for (int q = 0; q < 4; ++q) c[ms][j][q] = 0.f;

    for (int k = 0; k < 5; ++k) {
        const float* xhp = xh + (mw * 32 + (lane >> 2) + k) * 132 + (lane & 3);
        const float* xlp = xl + (mw * 32 + (lane >> 2) + k) * 132 + (lane & 3);
        const float* whp = wh + (nw * 32 + (lane >> 2)) * 132 + (lane & 3);
        const float* wlp = wl + (nw * 32 + (lane >> 2)) * 132 + (lane & 3);
#pragma unroll 2
        for (int ks = 0; ks < 16; ++ks) {
            const int kb = ks * 8;
            unsigned ah[2][4], al[2][4], bh[4][2], bl[4][2];
#pragma unroll
            for (int ms = 0; ms < 2; ++ms) {
                int base = ms * 16 * 132 + kb;
                ah[ms][0] = __float_as_uint(xhp[base]);
                ah[ms][1] = __float_as_uint(xhp[base + 8 * 132]);
                ah[ms][2] = __float_as_uint(xhp[base + 4]);
                ah[ms][3] = __float_as_uint(xhp[base + 8 * 132 + 4]);
                al[ms][0] = __float_as_uint(xlp[base]);
                al[ms][1] = __float_as_uint(xlp[base + 8 * 132]);
                al[ms][2] = __float_as_uint(xlp[base + 4]);
                al[ms][3] = __float_as_uint(xlp[base + 8 * 132 + 4]);
            }
#pragma unroll
            for (int j = 0; j < 4; ++j) {
                int base = j * 8 * 132 + kb;
                bh[j][0] = __float_as_uint(whp[base]);
                bh[j][1] = __float_as_uint(whp[base + 4]);
                bl[j][0] = __float_as_uint(wlp[base]);
                bl[j][1] = __float_as_uint(wlp[base + 4]);
            }
#pragma unroll
            for (int ms = 0; ms < 2; ++ms)
#pragma unroll
                for (int j = 0; j < 4; ++j) {
                    mma_tf32(c[ms][j], ah[ms][0], ah[ms][1], ah[ms][2], ah[ms][3],
                             bh[j][0], bh[j][1]);
                    mma_tf32(c[ms][j], al[ms][0], al[ms][1], al[ms][2], al[ms][3],
                             bh[j][0], bh[j][1]);
                    mma_tf32(c[ms][j], ah[ms][0], ah[ms][1], ah[ms][2], ah[ms][3],
                             bl[j][0], bl[j][1]);
                }
        }
        __syncthreads();
        if (k < 4) { fillW(k + 1); __syncthreads(); }
    }

    // ---- epilogue: C -> smem (reuse xh, stride 68) -> BN+pool+relu ----
    float* convS = xh;
#pragma unroll
    for (int ms = 0; ms < 2; ++ms)
#pragma unroll
        for (int j = 0; j < 4; ++j) {
            int row = mw * 32 + ms * 16 + (lane >> 2);
            int col = nw * 32 + j * 8 + 2 * (lane & 3);
            convS[row * 68 + col]           = c[ms][j][0];
            convS[row * 68 + col + 1]       = c[ms][j][1];
            convS[(row + 8) * 68 + col]     = c[ms][j][2];
            convS[(row + 8) * 68 + col + 1] = c[ms][j][3];
        }
    __syncthreads();
    for (int idx = tid; idx < 42 * 64; idx += 256) {
        int oc = idx & 63, pl = idx >> 6;
        int p = bx * 42 + pl;
        if (p < L2P) {
            float sc = scS[oc], sh = shS[oc];
            float y0 = fmaf(convS[(3 * pl) * 68 + oc],     sc, sh);
            float y1 = fmaf(convS[(3 * pl + 1) * 68 + oc], sc, sh);
            float y2 = fmaf(convS[(3 * pl + 2) * 68 + oc], sc, sh);
            g_h2T[(b * L2P + p) * C2 + oc] = fmaxf(fmaxf(fmaxf(y0, y1), y2), 0.f);
        }
    }
}

// ============================================================
// Kernel 3: conv3 (64->64, k3) + BN + pool(3,2) + relu -> g_h3T[feat][b]
// (R6 best) 16 ocd x 16 gg; 4 oc x 7 conv (3 pooled) per thread.
// ============================================================
__global__ void __launch_bounds__(256, 2) k_conv3(
        const float* __restrict__ bias,
        const float* __restrict__ bng,
        const float* __restrict__ bnb,
        const float* __restrict__ bnm,
        const float* __restrict__ bnv) {
    __shared__ float xs[2][99][20];
    __shared__ ull   ws[2][1536];     // [k*8+icp][oc]

    const int b   = blockIdx.y;
    const int ct0 = blockIdx.x * 96;
    const int tid = threadIdx.x;
    const int ocd = tid & 15;
    const int gg  = tid >> 4;

    ull acc[4][7];
#pragma unroll
    for (int q = 0; q < 4; ++q)
#pragma unroll
        for (int m = 0; m < 7; ++m) acc[q][m] = 0ull;

    auto fill = [&](int c, int bi) {
        const int ic0 = c * 16;
        for (int idx = tid; idx < 99 * 4; idx += 256) {
            int j = idx >> 2, q = idx & 3;
            int t = ct0 + j;
            float* dst = &xs[bi][j][q * 4];
            if (t < L2P) cpa16(dst, &g_h2T[(b * L2P + t) * C2 + ic0 + q * 4]);
            else { dst[0] = 0.f; dst[1] = 0.f; dst[2] = 0.f; dst[3] = 0.f; }
        }
        for (int idx = tid; idx < 1536; idx += 256) {
            int oc = idx & 63, r = idx >> 6;     // r = k*8+icp
            cpa8(&ws[bi][idx], &g_w3T[((r >> 3) * 64 + oc) * 64 + ic0 + 2 * (r & 7)]);
        }
    };

    fill(0, 0); CP_COMMIT();
    for (int c = 0; c < 4; ++c) {
        if (c + 1 < 4) { fill(c + 1, (c + 1) & 1); CP_COMMIT(); CP_WAIT1(); }
        else           { CP_WAIT0(); }
        __syncthreads();
        const int bi = c & 1;
#pragma unroll 1
        for (int icp = 0; icp < 8; ++icp) {
            ull xd[9];
#pragma unroll
            for (int j = 0; j < 9; ++j)
                xd[j] = *(const ull*)&xs[bi][6 * gg + j][2 * icp];
            ull wv[4][3];
#pragma unroll
            for (int k = 0; k < 3; ++k) {
#pragma unroll
                for (int q = 0; q < 4; ++q)
                    wv[q][k] = ws[bi][(k * 8 + icp) * 64 + ocd + 16 * q];
            }
#pragma unroll
            for (int m = 0; m < 7; ++m)
#pragma unroll
                for (int k = 0; k < 3; ++k)
#pragma unroll
                    for (int q = 0; q < 4; ++q)
                        fma2(acc[q][m], wv[q][k], xd[m + k]);
        }
        __syncthreads();
    }

#pragma unroll
    for (int q = 0; q < 4; ++q) {
        int oc = ocd + 16 * q;
        float scale = bng[oc] / sqrtf(bnv[oc] + EPS_BN);
        float shift = bnb[oc] + (bias[oc] - bnm[oc]) * scale;
#pragma unroll
        for (int j = 0; j < 3; ++j) {
            int p = blockIdx.x * 48 + 3 * gg + j;
            if (p >= L3P) continue;
            ull a0 = acc[q][2 * j], a1 = acc[q][2 * j + 1], a2 = acc[q][2 * j + 2];
            float y0 = fmaf(lo32(a0) + hi32(a0), scale, shift);
            float y1 = fmaf(lo32(a1) + hi32(a1), scale, shift);
            float y2 = fmaf(lo32(a2) + hi32(a2), scale, shift);
            float y = fmaxf(fmaxf(fmaxf(y0, y1), y2), 0.f);
            g_h3T[(oc * L3P + p) * BATCH + b] = y;
        }
    }
}

// ============================================================
// Kernel 4a: fc1 split-K. 256 blocks x 42-wide K chunks.
// ============================================================
__global__ void __launch_bounds__(256) k_fcA(const float* __restrict__ fc1w) {
    const int chunk = blockIdx.x;
    const int r = threadIdx.x;
    __shared__ float wsS[42][48];

    for (int idx = r; idx < 42 * 48; idx += 256) {
        int o = idx / 42, k = idx % 42;
        wsS[k][o] = fc1w[o * FCIN + chunk * 42 + k];
    }
    __syncthreads();

    ull acc[24];
#pragma unroll
    for (int p = 0; p < 24; ++p) acc[p] = 0ull;

#pragma unroll 2
    for (int k = 0; k < 42; ++k) {
        float xv = g_h3T[(chunk * 42 + k) * BATCH + r];
        ull xd = dup2(xv);
#pragma unroll
        for (int p = 0; p < 24; ++p)
            fma2(acc[p], *(const ull*)&wsS[k][2 * p], xd);
    }
    float* outp = &g_part[(chunk * BATCH + r) * 48];
#pragma unroll
    for (int p = 0; p < 24; ++p) {
        outp[2 * p]     = lo32(acc[p]);
        outp[2 * p + 1] = hi32(acc[p]);
    }
}

// ============================================================
// Kernel 4b: reduce + fc2/fc3/fc4 + tanh
// ============================================================
__global__ void k_fcB(const float* __restrict__ fc1b,
                      const float* __restrict__ fc2w, const float* __restrict__ fc2b,
                      const float* __restrict__ fc3w, const float* __restrict__ fc3b,
                      const float* __restrict__ fc4w, const float* __restrict__ fc4b) {
    const int r = blockIdx.x;
    const int t = threadIdx.x;
    __shared__ float s1[48], s2[32], s3[16];

    if (t < 48) {
        float a = 0.f;
#pragma unroll 8
        for (int c = 0; c < 256; ++c)
            a += g_part[(c * BATCH + r) * 48 + t];
        s1[t] = fmaxf(a + fc1b[t], 0.f);
    }
    __syncthreads();
    if (t < 32) {
        float a2 = 0.f;
#pragma unroll
        for (int k = 0; k < 48; ++k) a2 = fmaf(s1[k], fc2w[t * 48 + k], a2);
        s2[t] = fmaxf(a2 + fc2b[t], 0.f);
    }
    __syncthreads();
    if (t < 16) {
        float a3 = 0.f;
#pragma unroll
        for (int k = 0; k < 32; ++k) a3 = fmaf(s2[k], fc3w[t * 32 + k], a3);
        s3[t] = fmaxf(a3 + fc3b[t], 0.f);
    }
    __syncthreads();
    if (t < 5) {
        float a4 = 0.f;
#pragma unroll
        for (int k = 0; k < 16; ++k) a4 = fmaf(s3[k], fc4w[t * 16 + k], a4);
        g_theta[r * 5 + t] = tanhf(a4 + fc4b[t]);
    }
}

// ============================================================
// Kernel 5: CPAB integrate + resample
// ============================================================
__global__ void k_warp(const float* __restrict__ x,
                       const float* __restrict__ basis,
                       float* __restrict__ out) {
    const int b   = blockIdx.x;
    const int tid = threadIdx.x;
    __shared__ float sa[6], sb[6];
    if (tid < 12) {
        float a = 0.f;
#pragma unroll
        for (int k = 0; k < 5; ++k)
            a = fmaf(g_theta[b * 5 + k], basis[tid * 5 + k], a);
        if (tid & 1) sb[tid >> 1] = a; else sa[tid >> 1] = a;
    }
    __syncthreads();
    float la[6], lb[6];
#pragma unroll
    for (int c = 0; c < 6; ++c) { la[c] = sa[c]; lb[c] = sb[c]; }
    const float INF = __int_as_float(0x7f800000);

    for (int r = 0; r < 8; ++r) {
        int i = tid + r * 256;
        float xv = (float)i / 2047.0f;
        float t = 1.0f;
#pragma unroll 1
        for (int it = 0; it < 7; ++it) {
            int c = (int)floorf(xv * 6.0f);
            c = c < 0 ? 0 : (c > 5 ? 5 : c);
            float a  = la[c];
            float bc = lb[c];
            float v  = fmaf(a, xv, bc);
            float xb = (v >= 0.f) ? (float)(c + 1) / 6.0f : (float)c / 6.0f;
            bool  big = fabsf(a) > 1e-8f;
            float a_s = big ? a : 1.0f;
            float boa = bc / a_s;
            float z   = xv + boa;
            float zb  = xb + boa;
            float zden  = (fabsf(z) > 1e-12f) ? z : 1e-12f;
            float ratio = zb / zden;
            float t_exp = logf(fmaxf(ratio, 1e-12f)) / a_s;
            float v_s   = (fabsf(v) > 1e-12f) ? v : 1.0f;
            float t_lin = (xb - xv) / v_s;
            float thit  = big ? t_exp : t_lin;
            bool valid = (fabsf(v) > 1e-12f) && (thit > 0.f) &&
                         ((big ? ratio : 1.0f) > 0.f);
            thit = valid ? thit : INF;
            float tau = fminf(t, thit);
            float x_new = big ? (z * expf(a * tau) - (z - xv))
                              : fmaf(bc, tau, xv);
            bool hit = (thit <= t);
            float nudge = (v >= 0.f) ? 1e-6f : -1e-6f;
            xv = hit ? (xb + nudge) : x_new;
            xv = fminf(fmaxf(xv, 0.f), 1.f);
            t = fmaxf(t - tau, 0.f);
        }
        float p = fminf(fmaxf(xv, 0.f), 1.f) * 2047.0f;
        int x0 = (int)floorf(p);
        x0 = x0 < 0 ? 0 : (x0 > 2046 ? 2046 : x0);
        float wgt = p - (float)x0;
#pragma unroll
        for (int ch = 0; ch < 3; ++ch) {
            float d0 = x[(b * 3 + ch) * SIGLEN + x0];
            float d1 = x[(b * 3 + ch) * SIGLEN + x0 + 1];
            out[(b * 3 + ch) * SIGLEN + i] = d0 * (1.0f - wgt) + d1 * wgt;
        }
    }
}

// ============================================================
extern "C" void kernel_launch(void* const* d_in, const int* in_sizes, int n_in,
                              void* d_out, int out_size) {
    const float* x     = (const float*)d_in[0];
    const float* c1w   = (const float*)d_in[1];
    const float* c1b   = (const float*)d_in[2];
    const float* bn1g  = (const float*)d_in[3];
    const float* bn1b  = (const float*)d_in[4];
    const float* bn1m  = (const float*)d_in[5];
    const float* bn1v  = (const float*)d_in[6];
    const float* c2w   = (const float*)d_in[7];
    const float* c2b   = (const float*)d_in[8];
    const float* bn2g  = (const float*)d_in[9];
    const float* bn2b  = (const float*)d_in[10];
    const float* bn2m  = (const float*)d_in[11];
    const float* bn2v  = (const float*)d_in[12];
    const float* c3w   = (const float*)d_in[13];
    const float* c3b   = (const float*)d_in[14];
    const float* bn3g  = (const float*)d_in[15];
    const float* bn3b  = (const float*)d_in[16];
    const float* bn3m  = (const float*)d_in[17];
    const float* bn3v  = (const float*)d_in[18];
    const float* fc1w  = (const float*)d_in[19];
    const float* fc1b  = (const float*)d_in[20];
    const float* fc2w  = (const float*)d_in[21];
    const float* fc2b  = (const float*)d_in[22];
    const float* fc3w  = (const float*)d_in[23];
    const float* fc3b  = (const float*)d_in[24];
    const float* fc4w  = (const float*)d_in[25];
    const float* fc4b  = (const float*)d_in[26];
    const float* basis = (const float*)d_in[27];
    float* out = (float*)d_out;

    static int attr_done = 0;
    if (!attr_done) {
        cudaFuncSetAttribute(k_conv2mma,
                             cudaFuncAttributeMaxDynamicSharedMemorySize, CV2_SMEM);
        attr_done = 1;
    }

    k_prep<<<160, 256>>>(c2w, c3w);
    dim3 g1(16, BATCH);  k_conv1<<<g1, 128>>>(x, c1w, c1b, bn1g, bn1b, bn1m, bn1v);
    dim3 g2(9,  BATCH);  k_conv2mma<<<g2, 256, CV2_SMEM>>>(c2b, bn2g, bn2b, bn2m, bn2v);
    dim3 g3(4,  BATCH);  k_conv3<<<g3, 256>>>(c3b, bn3g, bn3b, bn3m, bn3v);
    k_fcA<<<256, 256>>>(fc1w);
    k_fcB<<<BATCH, 64>>>(fc1b, fc2w, fc2b, fc3w, fc3b, fc4w, fc4b);
    k_warp<<<BATCH, 256>>>(x, basis, out);
}

// round 10
// speedup vs baseline: 1.5874x; 1.1486x over previous
#include <cuda_runtime.h>
#include <math.h>
#include <stdint.h>

#define BATCH 256
#define SIGLEN 2048
#define L1P 1022
#define L2P 339
#define L3P 168
#define C1 128
#define C2 64
#define C3 64
#define FCIN 10752
#define EPS_BN 1e-5f

typedef unsigned long long ull;

// ---- scratch ----
__device__ float g_h1T[BATCH * L1P * C1];   // [b][pos][ic]
__device__ float g_h2T[BATCH * L2P * C2];   // [b][pos][oc]
__device__ float g_h3T[FCIN * BATCH];       // [feature][batch]
__device__ float g_w2T[5 * 64 * 128];       // [k][oc][ic]
__device__ float g_w3T[3 * 64 * 64];        // [k][oc][ic]
__device__ float g_part[256 * BATCH * 48];
__device__ float g_theta[BATCH * 5];

__device__ __forceinline__ void fma2(ull& d, ull a, ull b) {
    asm("fma.rn.f32x2 %0, %1, %2, %0;" : "+l"(d) : "l"(a), "l"(b));
}
__device__ __forceinline__ ull dup2(float v) {
    ull r; asm("mov.b64 %0, {%1, %1};" : "=l"(r) : "f"(v)); return r;
}
__device__ __forceinline__ float lo32(ull v) { return __uint_as_float((unsigned)v); }
__device__ __forceinline__ float hi32(ull v) { return __uint_as_float((unsigned)(v >> 32)); }

__device__ __forceinline__ void cpa16(void* dst, const void* src) {
    unsigned d = (unsigned)__cvta_generic_to_shared(dst);
    asm volatile("cp.async.cg.shared.global [%0], [%1], 16;" :: "r"(d), "l"(src));
}
__device__ __forceinline__ void cpa8(void* dst, const void* src) {
    unsigned d = (unsigned)__cvta_generic_to_shared(dst);
    asm volatile("cp.async.ca.shared.global [%0], [%1], 8;" :: "r"(d), "l"(src));
}
#define CP_COMMIT()  asm volatile("cp.async.commit_group;" ::: "memory")
#define CP_WAIT1()   asm volatile("cp.async.wait_group 1;" ::: "memory")
#define CP_WAIT0()   asm volatile("cp.async.wait_group 0;" ::: "memory")

__device__ __forceinline__ float f2tf_f(float v) {
    unsigned r; asm("cvt.rna.tf32.f32 %0, %1;" : "=r"(r) : "f"(v));
    return __uint_as_float(r);
}
__device__ __forceinline__ void tfsplit(float v, unsigned& h, unsigned& l) {
    float hf = f2tf_f(v);
    h = __float_as_uint(hf);
    l = __float_as_uint(f2tf_f(v - hf));
}
__device__ __forceinline__ void mma_tf32(float* d,
        unsigned a0, unsigned a1, unsigned a2, unsigned a3,
        unsigned b0, unsigned b1) {
    asm("mma.sync.aligned.m16n8k8.row.col.f32.tf32.tf32.f32 "
        "{%0,%1,%2,%3}, {%4,%5,%6,%7}, {%8,%9}, {%0,%1,%2,%3};"
        : "+f"(d[0]), "+f"(d[1]), "+f"(d[2]), "+f"(d[3])
        : "r"(a0), "r"(a1), "r"(a2), "r"(a3), "r"(b0), "r"(b1));
}

// ============================================================
// Kernel 0: weight transposes
// ============================================================
__global__ void k_prep(const float* __restrict__ w2, const float* __restrict__ w3) {
    int i = blockIdx.x * blockDim.x + threadIdx.x;
    if (i < 5 * 64 * 128) {
        int k = i >> 13, oc = (i >> 7) & 63, ic = i & 127;
        g_w2T[i] = w2[oc * 640 + ic * 5 + k];
    }
    if (i < 3 * 64 * 64) {
        int k = i >> 12, oc = (i >> 6) & 63, ic = i & 63;
        g_w3T[i] = w3[oc * 192 + ic * 3 + k];
    }
}

// ============================================================
// Kernel 1: conv1 (3->128, k3) + BN + pool(3,2) + relu -> g_h1T[b][pos][ic]
// ============================================================
__global__ void __launch_bounds__(128) k_conv1(
        const float* __restrict__ x,
        const float* __restrict__ w,
        const float* __restrict__ bias,
        const float* __restrict__ bng,
        const float* __restrict__ bnb,
        const float* __restrict__ bnm,
        const float* __restrict__ bnv) {
    const int b  = blockIdx.y;
    const int p0 = blockIdx.x * 64;
    const int oc = threadIdx.x;
    __shared__ float xs[3][132];
    __shared__ float outS[64][128];

    const int t0 = 2 * p0;
    for (int idx = threadIdx.x; idx < 3 * 131; idx += 128) {
        int ch = idx / 131, j = idx % 131;
        int t = t0 + j;
        xs[ch][j] = (t < SIGLEN) ? x[(b * 3 + ch) * SIGLEN + t] : 0.f;
    }
    float wr[9];
#pragma unroll
    for (int j = 0; j < 9; ++j) wr[j] = w[oc * 9 + j];
    float scale = bng[oc] / sqrtf(bnv[oc] + EPS_BN);
    float shift = bnb[oc] + (bias[oc] - bnm[oc]) * scale;
    __syncthreads();

#pragma unroll 4
    for (int pl = 0; pl < 64; ++pl) {
        float c0 = 0.f, c1 = 0.f, c2 = 0.f;
        int base = 2 * pl;
#pragma unroll
        for (int ch = 0; ch < 3; ++ch)
#pragma unroll
            for (int k = 0; k < 3; ++k) {
                float wv = wr[ch * 3 + k];
                c0 = fmaf(wv, xs[ch][base + k], c0);
                c1 = fmaf(wv, xs[ch][base + 1 + k], c1);
                c2 = fmaf(wv, xs[ch][base + 2 + k], c2);
            }
        float y0 = fmaf(c0, scale, shift);
        float y1 = fmaf(c1, scale, shift);
        float y2 = fmaf(c2, scale, shift);
        outS[pl][oc] = fmaxf(fmaxf(fmaxf(y0, y1), y2), 0.f);
    }
    __syncthreads();
    for (int idx = threadIdx.x; idx < 64 * 128; idx += 128) {
        int pl = idx >> 7, col = idx & 127;
        int p = p0 + pl;
        if (p < L1P) g_h1T[(b * L1P + p) * C1 + col] = outS[pl][col];
    }
}

// ============================================================
// Kernel 2: conv2 via mma.sync tf32 3x-split implicit GEMM  [HOT]
// f32 single-copy smem (104 KB -> 2 blocks/SM); tf32 hi/lo split done
// in registers at fragment load. 8 warps: 4 M-groups x 2 N-groups.
// grid (9, 256).
// ============================================================
#define CV2_SMEM ((17424 + 8448 + 128) * 4)   // 104,000 B

__global__ void __launch_bounds__(256, 2) k_conv2mma(
        const float* __restrict__ bias,
        const float* __restrict__ bng,
        const float* __restrict__ bnb,
        const float* __restrict__ bnm,
        const float* __restrict__ bnv) {
    extern __shared__ float sm[];
    float* xf  = sm;               // [132][132] f32
    float* wf  = sm + 17424;       // [64][132]  f32
    float* scS = sm + 25872;       // [64]
    float* shS = sm + 25936;       // [64]

    const int b    = blockIdx.y;
    const int bx   = blockIdx.x;
    const int ct0  = bx * 126;
    const int tid  = threadIdx.x;
    const int lane = tid & 31;
    const int wid  = tid >> 5;
    const int mw   = wid & 3;      // M group (32 rows)
    const int nw   = wid >> 2;     // N group (32 cols)

    if (tid < 64) {
        float sc = bng[tid] * rsqrtf(bnv[tid] + EPS_BN);
        scS[tid] = sc;
        shS[tid] = bnb[tid] + (bias[tid] - bnm[tid]) * sc;
    }

    // ---- stage X (132 rows x 128 ic) f32 via cp.async ----
    const float* h1b = &g_h1T[(size_t)b * L1P * C1];
    for (int idx = tid; idx < 132 * 32; idx += 256) {
        int j = idx >> 5, icq = idx & 31;
        int t = ct0 + j;
        float* dst = xf + j * 132 + icq * 4;
        if (t < L1P) cpa16(dst, h1b + (size_t)t * C1 + icq * 4);
        else { dst[0] = 0.f; dst[1] = 0.f; dst[2] = 0.f; dst[3] = 0.f; }
    }
    auto fillW = [&](int k) {
        for (int idx = tid; idx < 64 * 32; idx += 256) {
            int oc = idx >> 5, icq = idx & 31;
            cpa16(wf + oc * 132 + icq * 4, g_w2T + (k * 64 + oc) * 128 + icq * 4);
        }
    };
    fillW(0);
    CP_COMMIT(); CP_WAIT0();
    __syncthreads();

    float c[2][4][4];
#pragma unroll
    for (int ms = 0; ms < 2; ++ms)
#pragma unroll
        for (int j = 0; j < 4; ++j)
#pragma unroll
            for (int q = 0; q < 4; ++q) c[ms][j][q] = 0.f;

    for (int k = 0; k < 5; ++k) {
        const float* xfp = xf + (mw * 32 + (lane >> 2) + k) * 132 + (lane & 3);
        const float* wfp = wf + (nw * 32 + (lane >> 2)) * 132 + (lane & 3);
#pragma unroll 2
        for (int ks = 0; ks < 16; ++ks) {
            const int kb = ks * 8;
            unsigned ah[2][4], al[2][4], bh[4][2], bl[4][2];
#pragma unroll
            for (int ms = 0; ms < 2; ++ms) {
                int base = ms * 16 * 132 + kb;
                tfsplit(xfp[base],               ah[ms][0], al[ms][0]);
                tfsplit(xfp[base + 8 * 132],     ah[ms][1], al[ms][1]);
                tfsplit(xfp[base + 4],           ah[ms][2], al[ms][2]);
                tfsplit(xfp[base + 8 * 132 + 4], ah[ms][3], al[ms][3]);
            }
#pragma unroll
            for (int j = 0; j < 4; ++j) {
                int base = j * 8 * 132 + kb;
                tfsplit(wfp[base],     bh[j][0], bl[j][0]);
                tfsplit(wfp[base + 4], bh[j][1], bl[j][1]);
            }
#pragma unroll
            for (int ms = 0; ms < 2; ++ms)
#pragma unroll
                for (int j = 0; j < 4; ++j) {
                    mma_tf32(c[ms][j], ah[ms][0], ah[ms][1], ah[ms][2], ah[ms][3],
                             bh[j][0], bh[j][1]);
                    mma_tf32(c[ms][j], al[ms][0], al[ms][1], al[ms][2], al[ms][3],
                             bh[j][0], bh[j][1]);
                    mma_tf32(c[ms][j], ah[ms][0], ah[ms][1], ah[ms][2], ah[ms][3],
                             bl[j][0], bl[j][1]);
                }
        }
        if (k < 4) {
            __syncthreads();
            fillW(k + 1);
            CP_COMMIT(); CP_WAIT0();
            __syncthreads();
        }
    }
    __syncthreads();

    // ---- epilogue: C -> smem (reuse xf, stride 68) -> BN+pool+relu ----
    float* convS = xf;
#pragma unroll
    for (int ms = 0; ms < 2; ++ms)
#pragma unroll
        for (int j = 0; j < 4; ++j) {
            int row = mw * 32 + ms * 16 + (lane >> 2);
            int col = nw * 32 + j * 8 + 2 * (lane & 3);
            convS[row * 68 + col]           = c[ms][j][0];
            convS[row * 68 + col + 1]       = c[ms][j][1];
            convS[(row + 8) * 68 + col]     = c[ms][j][2];
            convS[(row + 8) * 68 + col + 1] = c[ms][j][3];
        }
    __syncthreads();
    for (int idx = tid; idx < 42 * 64; idx += 256) {
        int oc = idx & 63, pl = idx >> 6;
        int p = bx * 42 + pl;
        if (p < L2P) {
            float sc = scS[oc], sh = shS[oc];
            float y0 = fmaf(convS[(3 * pl) * 68 + oc],     sc, sh);
            float y1 = fmaf(convS[(3 * pl + 1) * 68 + oc], sc, sh);
            float y2 = fmaf(convS[(3 * pl + 2) * 68 + oc], sc, sh);
            g_h2T[(b * L2P + p) * C2 + oc] = fmaxf(fmaxf(fmaxf(y0, y1), y2), 0.f);
        }
    }
}

// ============================================================
// Kernel 3: conv3 (64->64, k3) + BN + pool(3,2) + relu -> g_h3T[feat][b]
// (R6 best) 16 ocd x 16 gg; 4 oc x 7 conv (3 pooled) per thread.
// ============================================================
__global__ void __launch_bounds__(256, 2) k_conv3(
        const float* __restrict__ bias,
        const float* __restrict__ bng,
        const float* __restrict__ bnb,
        const float* __restrict__ bnm,
        const float* __restrict__ bnv) {
    __shared__ float xs[2][99][20];
    __shared__ ull   ws[2][1536];     // [k*8+icp][oc]

    const int b   = blockIdx.y;
    const int ct0 = blockIdx.x * 96;
    const int tid = threadIdx.x;
    const int ocd = tid & 15;
    const int gg  = tid >> 4;

    ull acc[4][7];
#pragma unroll
    for (int q = 0; q < 4; ++q)
#pragma unroll
        for (int m = 0; m < 7; ++m) acc[q][m] = 0ull;

    auto fill = [&](int c, int bi) {
        const int ic0 = c * 16;
        for (int idx = tid; idx < 99 * 4; idx += 256) {
            int j = idx >> 2, q = idx & 3;
            int t = ct0 + j;
            float* dst = &xs[bi][j][q * 4];
            if (t < L2P) cpa16(dst, &g_h2T[(b * L2P + t) * C2 + ic0 + q * 4]);
            else { dst[0] = 0.f; dst[1] = 0.f; dst[2] = 0.f; dst[3] = 0.f; }
        }
        for (int idx = tid; idx < 1536; idx += 256) {
            int oc = idx & 63, r = idx >> 6;     // r = k*8+icp
            cpa8(&ws[bi][idx], &g_w3T[((r >> 3) * 64 + oc) * 64 + ic0 + 2 * (r & 7)]);
        }
    };

    fill(0, 0); CP_COMMIT();
    for (int c = 0; c < 4; ++c) {
        if (c + 1 < 4) { fill(c + 1, (c + 1) & 1); CP_COMMIT(); CP_WAIT1(); }
        else           { CP_WAIT0(); }
        __syncthreads();
        const int bi = c & 1;
#pragma unroll 1
        for (int icp = 0; icp < 8; ++icp) {
            ull xd[9];
#pragma unroll
            for (int j = 0; j < 9; ++j)
                xd[j] = *(const ull*)&xs[bi][6 * gg + j][2 * icp];
            ull wv[4][3];
#pragma unroll
            for (int k = 0; k < 3; ++k) {
#pragma unroll
                for (int q = 0; q < 4; ++q)
                    wv[q][k] = ws[bi][(k * 8 + icp) * 64 + ocd + 16 * q];
            }
#pragma unroll
            for (int m = 0; m < 7; ++m)
#pragma unroll
                for (int k = 0; k < 3; ++k)
#pragma unroll
                    for (int q = 0; q < 4; ++q)
                        fma2(acc[q][m], wv[q][k], xd[m + k]);
        }
        __syncthreads();
    }

#pragma unroll
    for (int q = 0; q < 4; ++q) {
        int oc = ocd + 16 * q;
        float scale = bng[oc] / sqrtf(bnv[oc] + EPS_BN);
        float shift = bnb[oc] + (bias[oc] - bnm[oc]) * scale;
#pragma unroll
        for (int j = 0; j < 3; ++j) {
            int p = blockIdx.x * 48 + 3 * gg + j;
            if (p >= L3P) continue;
            ull a0 = acc[q][2 * j], a1 = acc[q][2 * j + 1], a2 = acc[q][2 * j + 2];
            float y0 = fmaf(lo32(a0) + hi32(a0), scale, shift);
            float y1 = fmaf(lo32(a1) + hi32(a1), scale, shift);
            float y2 = fmaf(lo32(a2) + hi32(a2), scale, shift);
            float y = fmaxf(fmaxf(fmaxf(y0, y1), y2), 0.f);
            g_h3T[(oc * L3P + p) * BATCH + b] = y;
        }
    }
}

// ============================================================
// Kernel 4a: fc1 split-K. 256 blocks x 42-wide K chunks.
// ============================================================
__global__ void __launch_bounds__(256) k_fcA(const float* __restrict__ fc1w) {
    const int chunk = blockIdx.x;
    const int r = threadIdx.x;
    __shared__ float wsS[42][48];

    for (int idx = r; idx < 42 * 48; idx += 256) {
        int o = idx / 42, k = idx % 42;
        wsS[k][o] = fc1w[o * FCIN + chunk * 42 + k];
    }
    __syncthreads();

    ull acc[24];
#pragma unroll
    for (int p = 0; p < 24; ++p) acc[p] = 0ull;

#pragma unroll 2
    for (int k = 0; k < 42; ++k) {
        float xv = g_h3T[(chunk * 42 + k) * BATCH + r];
        ull xd = dup2(xv);
#pragma unroll
        for (int p = 0; p < 24; ++p)
            fma2(acc[p], *(const ull*)&wsS[k][2 * p], xd);
    }
    float* outp = &g_part[(chunk * BATCH + r) * 48];
#pragma unroll
    for (int p = 0; p < 24; ++p) {
        outp[2 * p]     = lo32(acc[p]);
        outp[2 * p + 1] = hi32(acc[p]);
    }
}

// ============================================================
// Kernel 4b: reduce + fc2/fc3/fc4 + tanh
// ============================================================
__global__ void k_fcB(const float* __restrict__ fc1b,
                      const float* __restrict__ fc2w, const float* __restrict__ fc2b,
                      const float* __restrict__ fc3w, const float* __restrict__ fc3b,
                      const float* __restrict__ fc4w, const float* __restrict__ fc4b) {
    const int r = blockIdx.x;
    const int t = threadIdx.x;
    __shared__ float s1[48], s2[32], s3[16];

    if (t < 48) {
        float a = 0.f;
#pragma unroll 8
        for (int c = 0; c < 256; ++c)
            a += g_part[(c * BATCH + r) * 48 + t];
        s1[t] = fmaxf(a + fc1b[t], 0.f);
    }
    __syncthreads();
    if (t < 32) {
        float a2 = 0.f;
#pragma unroll
        for (int k = 0; k < 48; ++k) a2 = fmaf(s1[k], fc2w[t * 48 + k], a2);
        s2[t] = fmaxf(a2 + fc2b[t], 0.f);
    }
    __syncthreads();
    if (t < 16) {
        float a3 = 0.f;
#pragma unroll
        for (int k = 0; k < 32; ++k) a3 = fmaf(s2[k], fc3w[t * 32 + k], a3);
        s3[t] = fmaxf(a3 + fc3b[t], 0.f);
    }
    __syncthreads();
    if (t < 5) {
        float a4 = 0.f;
#pragma unroll
        for (int k = 0; k < 16; ++k) a4 = fmaf(s3[k], fc4w[t * 16 + k], a4);
        g_theta[r * 5 + t] = tanhf(a4 + fc4b[t]);
    }
}

// ============================================================
// Kernel 5: CPAB integrate + resample
// ============================================================
__global__ void k_warp(const float* __restrict__ x,
                       const float* __restrict__ basis,
                       float* __restrict__ out) {
    const int b   = blockIdx.x;
    const int tid = threadIdx.x;
    __shared__ float sa[6], sb[6];
    if (tid < 12) {
        float a = 0.f;
#pragma unroll
        for (int k = 0; k < 5; ++k)
            a = fmaf(g_theta[b * 5 + k], basis[tid * 5 + k], a);
        if (tid & 1) sb[tid >> 1] = a; else sa[tid >> 1] = a;
    }
    __syncthreads();
    float la[6], lb[6];
#pragma unroll
    for (int c = 0; c < 6; ++c) { la[c] = sa[c]; lb[c] = sb[c]; }
    const float INF = __int_as_float(0x7f800000);

    for (int r = 0; r < 8; ++r) {
        int i = tid + r * 256;
        float xv = (float)i / 2047.0f;
        float t = 1.0f;
#pragma unroll 1
        for (int it = 0; it < 7; ++it) {
            int c = (int)floorf(xv * 6.0f);
            c = c < 0 ? 0 : (c > 5 ? 5 : c);
            float a  = la[c];
            float bc = lb[c];
            float v  = fmaf(a, xv, bc);
            float xb = (v >= 0.f) ? (float)(c + 1) / 6.0f : (float)c / 6.0f;
            bool  big = fabsf(a) > 1e-8f;
            float a_s = big ? a : 1.0f;
            float boa = bc / a_s;
            float z   = xv + boa;
            float zb  = xb + boa;
            float zden  = (fabsf(z) > 1e-12f) ? z : 1e-12f;
            float ratio = zb / zden;
            float t_exp = logf(fmaxf(ratio, 1e-12f)) / a_s;
            float v_s   = (fabsf(v) > 1e-12f) ? v : 1.0f;
            float t_lin = (xb - xv) / v_s;
            float thit  = big ? t_exp : t_lin;
            bool valid = (fabsf(v) > 1e-12f) && (thit > 0.f) &&
                         ((big ? ratio : 1.0f) > 0.f);
            thit = valid ? thit : INF;
            float tau = fminf(t, thit);
            float x_new = big ? (z * expf(a * tau) - (z - xv))
                              : fmaf(bc, tau, xv);
            bool hit = (thit <= t);
            float nudge = (v >= 0.f) ? 1e-6f : -1e-6f;
            xv = hit ? (xb + nudge) : x_new;
            xv = fminf(fmaxf(xv, 0.f), 1.f);
            t = fmaxf(t - tau, 0.f);
        }
        float p = fminf(fmaxf(xv, 0.f), 1.f) * 2047.0f;
        int x0 = (int)floorf(p);
        x0 = x0 < 0 ? 0 : (x0 > 2046 ? 2046 : x0);
        float wgt = p - (float)x0;
#pragma unroll
        for (int ch = 0; ch < 3; ++ch) {
            float d0 = x[(b * 3 + ch) * SIGLEN + x0];
            float d1 = x[(b * 3 + ch) * SIGLEN + x0 + 1];
            out[(b * 3 + ch) * SIGLEN + i] = d0 * (1.0f - wgt) + d1 * wgt;
        }
    }
}

// ============================================================
extern "C" void kernel_launch(void* const* d_in, const int* in_sizes, int n_in,
                              void* d_out, int out_size) {
    const float* x     = (const float*)d_in[0];
    const float* c1w   = (const float*)d_in[1];
    const float* c1b   = (const float*)d_in[2];
    const float* bn1g  = (const float*)d_in[3];
    const float* bn1b  = (const float*)d_in[4];
    const float* bn1m  = (const float*)d_in[5];
    const float* bn1v  = (const float*)d_in[6];
    const float* c2w   = (const float*)d_in[7];
    const float* c2b   = (const float*)d_in[8];
    const float* bn2g  = (const float*)d_in[9];
    const float* bn2b  = (const float*)d_in[10];
    const float* bn2m  = (const float*)d_in[11];
    const float* bn2v  = (const float*)d_in[12];
    const float* c3w   = (const float*)d_in[13];
    const float* c3b   = (const float*)d_in[14];
    const float* bn3g  = (const float*)d_in[15];
    const float* bn3b  = (const float*)d_in[16];
    const float* bn3m  = (const float*)d_in[17];
    const float* bn3v  = (const float*)d_in[18];
    const float* fc1w  = (const float*)d_in[19];
    const float* fc1b  = (const float*)d_in[20];
    const float* fc2w  = (const float*)d_in[21];
    const float* fc2b  = (const float*)d_in[22];
    const float* fc3w  = (const float*)d_in[23];
    const float* fc3b  = (const float*)d_in[24];
    const float* fc4w  = (const float*)d_in[25];
    const float* fc4b  = (const float*)d_in[26];
    const float* basis = (const float*)d_in[27];
    float* out = (float*)d_out;

    static int attr_done = 0;
    if (!attr_done) {
        cudaFuncSetAttribute(k_conv2mma,
                             cudaFuncAttributeMaxDynamicSharedMemorySize, CV2_SMEM);
        attr_done = 1;
    }

    k_prep<<<160, 256>>>(c2w, c3w);
    dim3 g1(16, BATCH);  k_conv1<<<g1, 128>>>(x, c1w, c1b, bn1g, bn1b, bn1m, bn1v);
    dim3 g2(9,  BATCH);  k_conv2mma<<<g2, 256, CV2_SMEM>>>(c2b, bn2g, bn2b, bn2m, bn2v);
    dim3 g3(4,  BATCH);  k_conv3<<<g3, 256>>>(c3b, bn3g, bn3b, bn3m, bn3v);
    k_fcA<<<256, 256>>>(fc1w);
    k_fcB<<<BATCH, 64>>>(fc1b, fc2w, fc2b, fc3w, fc3b, fc4w, fc4b);
    k_warp<<<BATCH, 256>>>(x, basis, out);
}

// round 11
// speedup vs baseline: 1.6908x; 1.0652x over previous
#include <cuda_runtime.h>
#include <math.h>
#include <stdint.h>

#define BATCH 256
#define SIGLEN 2048
#define L1P 1022
#define L2P 339
#define L3P 168
#define C1 128
#define C2 64
#define C3 64
#define FCIN 10752
#define EPS_BN 1e-5f

typedef unsigned long long ull;

// ---- scratch ----
__device__ float g_h1T[BATCH * L1P * C1];   // [b][pos][ic]
__device__ float g_h2T[BATCH * L2P * C2];   // [b][pos][oc]
__device__ float g_h3T[FCIN * BATCH];       // [feature][batch]
__device__ float g_w2T[5 * 64 * 128];       // [k][oc][ic]
__device__ float g_w3T[3 * 64 * 64];        // [k][oc][ic]
__device__ float g_part[256 * BATCH * 48];
__device__ float g_theta[BATCH * 5];

__device__ __forceinline__ void fma2(ull& d, ull a, ull b) {
    asm("fma.rn.f32x2 %0, %1, %2, %0;" : "+l"(d) : "l"(a), "l"(b));
}
__device__ __forceinline__ ull dup2(float v) {
    ull r; asm("mov.b64 %0, {%1, %1};" : "=l"(r) : "f"(v)); return r;
}
__device__ __forceinline__ float lo32(ull v) { return __uint_as_float((unsigned)v); }
__device__ __forceinline__ float hi32(ull v) { return __uint_as_float((unsigned)(v >> 32)); }

__device__ __forceinline__ void cpa16(void* dst, const void* src) {
    unsigned d = (unsigned)__cvta_generic_to_shared(dst);
    asm volatile("cp.async.cg.shared.global [%0], [%1], 16;" :: "r"(d), "l"(src));
}
#define CP_COMMIT()  asm volatile("cp.async.commit_group;" ::: "memory")
#define CP_WAIT0()   asm volatile("cp.async.wait_group 0;" ::: "memory")

__device__ __forceinline__ float f2tf_f(float v) {
    unsigned r; asm("cvt.rna.tf32.f32 %0, %1;" : "=r"(r) : "f"(v));
    return __uint_as_float(r);
}
__device__ __forceinline__ void tfsplit(float v, unsigned& h, unsigned& l) {
    float hf = f2tf_f(v);
    h = __float_as_uint(hf);
    l = __float_as_uint(f2tf_f(v - hf));
}
__device__ __forceinline__ void mma_tf32(float* d,
        unsigned a0, unsigned a1, unsigned a2, unsigned a3,
        unsigned b0, unsigned b1) {
    asm("mma.sync.aligned.m16n8k8.row.col.f32.tf32.tf32.f32 "
        "{%0,%1,%2,%3}, {%4,%5,%6,%7}, {%8,%9}, {%0,%1,%2,%3};"
        : "+f"(d[0]), "+f"(d[1]), "+f"(d[2]), "+f"(d[3])
        : "r"(a0), "r"(a1), "r"(a2), "r"(a3), "r"(b0), "r"(b1));
}

// ============================================================
// Kernel 0: weight transposes
// ============================================================
__global__ void k_prep(const float* __restrict__ w2, const float* __restrict__ w3) {
    int i = blockIdx.x * blockDim.x + threadIdx.x;
    if (i < 5 * 64 * 128) {
        int k = i >> 13, oc = (i >> 7) & 63, ic = i & 127;
        g_w2T[i] = w2[oc * 640 + ic * 5 + k];
    }
    if (i < 3 * 64 * 64) {
        int k = i >> 12, oc = (i >> 6) & 63, ic = i & 63;
        g_w3T[i] = w3[oc * 192 + ic * 3 + k];
    }
}

// ============================================================
// Kernel 1: conv1 (3->128, k3) + BN + pool(3,2) + relu -> g_h1T[b][pos][ic]
// ============================================================
__global__ void __launch_bounds__(128) k_conv1(
        const float* __restrict__ x,
        const float* __restrict__ w,
        const float* __restrict__ bias,
        const float* __restrict__ bng,
        const float* __restrict__ bnb,
        const float* __restrict__ bnm,
        const float* __restrict__ bnv) {
    const int b  = blockIdx.y;
    const int p0 = blockIdx.x * 64;
    const int oc = threadIdx.x;
    __shared__ float xs[3][132];
    __shared__ float outS[64][128];

    const int t0 = 2 * p0;
    for (int idx = threadIdx.x; idx < 3 * 131; idx += 128) {
        int ch = idx / 131, j = idx % 131;
        int t = t0 + j;
        xs[ch][j] = (t < SIGLEN) ? x[(b * 3 + ch) * SIGLEN + t] : 0.f;
    }
    float wr[9];
#pragma unroll
    for (int j = 0; j < 9; ++j) wr[j] = w[oc * 9 + j];
    float scale = bng[oc] / sqrtf(bnv[oc] + EPS_BN);
    float shift = bnb[oc] + (bias[oc] - bnm[oc]) * scale;
    __syncthreads();

#pragma unroll 4
    for (int pl = 0; pl < 64; ++pl) {
        float c0 = 0.f, c1 = 0.f, c2 = 0.f;
        int base = 2 * pl;
#pragma unroll
        for (int ch = 0; ch < 3; ++ch)
#pragma unroll
            for (int k = 0; k < 3; ++k) {
                float wv = wr[ch * 3 + k];
                c0 = fmaf(wv, xs[ch][base + k], c0);
                c1 = fmaf(wv, xs[ch][base + 1 + k], c1);
                c2 = fmaf(wv, xs[ch][base + 2 + k], c2);
            }
        float y0 = fmaf(c0, scale, shift);
        float y1 = fmaf(c1, scale, shift);
        float y2 = fmaf(c2, scale, shift);
        outS[pl][oc] = fmaxf(fmaxf(fmaxf(y0, y1), y2), 0.f);
    }
    __syncthreads();
    for (int idx = threadIdx.x; idx < 64 * 128; idx += 128) {
        int pl = idx >> 7, col = idx & 127;
        int p = p0 + pl;
        if (p < L1P) g_h1T[(b * L1P + p) * C1 + col] = outS[pl][col];
    }
}

// ============================================================
// Kernel 2: conv2 via mma.sync tf32 3x-split implicit GEMM  [HOT]
// f32 single-copy smem (104 KB -> 2 blocks/SM); split in registers.
// 8 warps: 4 M-groups x 2 N-groups. grid (9, 256).
// ============================================================
#define CV2_SMEM ((17424 + 8448 + 128) * 4)   // 104,000 B

__global__ void __launch_bounds__(256, 2) k_conv2mma(
        const float* __restrict__ bias,
        const float* __restrict__ bng,
        const float* __restrict__ bnb,
        const float* __restrict__ bnm,
        const float* __restrict__ bnv) {
    extern __shared__ float sm[];
    float* xf  = sm;               // [132][132] f32
    float* wf  = sm + 17424;       // [64][132]  f32
    float* scS = sm + 25872;       // [64]
    float* shS = sm + 25936;       // [64]

    const int b    = blockIdx.y;
    const int bx   = blockIdx.x;
    const int ct0  = bx * 126;
    const int tid  = threadIdx.x;
    const int lane = tid & 31;
    const int wid  = tid >> 5;
    const int mw   = wid & 3;      // M group (32 rows)
    const int nw   = wid >> 2;     // N group (32 cols)

    if (tid < 64) {
        float sc = bng[tid] * rsqrtf(bnv[tid] + EPS_BN);
        scS[tid] = sc;
        shS[tid] = bnb[tid] + (bias[tid] - bnm[tid]) * sc;
    }

    const float* h1b = &g_h1T[(size_t)b * L1P * C1];
    for (int idx = tid; idx < 132 * 32; idx += 256) {
        int j = idx >> 5, icq = idx & 31;
        int t = ct0 + j;
        float* dst = xf + j * 132 + icq * 4;
        if (t < L1P) cpa16(dst, h1b + (size_t)t * C1 + icq * 4);
        else { dst[0] = 0.f; dst[1] = 0.f; dst[2] = 0.f; dst[3] = 0.f; }
    }
    auto fillW = [&](int k) {
        for (int idx = tid; idx < 64 * 32; idx += 256) {
            int oc = idx >> 5, icq = idx & 31;
            cpa16(wf + oc * 132 + icq * 4, g_w2T + (k * 64 + oc) * 128 + icq * 4);
        }
    };
    fillW(0);
    CP_COMMIT(); CP_WAIT0();
    __syncthreads();

    float c[2][4][4];
#pragma unroll
    for (int ms = 0; ms < 2; ++ms)
#pragma unroll
        for (int j = 0; j < 4; ++j)
#pragma unroll
            for (int q = 0; q < 4; ++q) c[ms][j][q] = 0.f;

    for (int k = 0; k < 5; ++k) {
        const float* xfp = xf + (mw * 32 + (lane >> 2) + k) * 132 + (lane & 3);
        const float* wfp = wf + (nw * 32 + (lane >> 2)) * 132 + (lane & 3);
#pragma unroll 2
        for (int ks = 0; ks < 16; ++ks) {
            const int kb = ks * 8;
            unsigned ah[2][4], al[2][4], bh[4][2], bl[4][2];
#pragma unroll
            for (int ms = 0; ms < 2; ++ms) {
                int base = ms * 16 * 132 + kb;
                tfsplit(xfp[base],               ah[ms][0], al[ms][0]);
                tfsplit(xfp[base + 8 * 132],     ah[ms][1], al[ms][1]);
                tfsplit(xfp[base + 4],           ah[ms][2], al[ms][2]);
                tfsplit(xfp[base + 8 * 132 + 4], ah[ms][3], al[ms][3]);
            }
#pragma unroll
            for (int j = 0; j < 4; ++j) {
                int base = j * 8 * 132 + kb;
                tfsplit(wfp[base],     bh[j][0], bl[j][0]);
                tfsplit(wfp[base + 4], bh[j][1], bl[j][1]);
            }
#pragma unroll
            for (int ms = 0; ms < 2; ++ms)
#pragma unroll
                for (int j = 0; j < 4; ++j) {
                    mma_tf32(c[ms][j], ah[ms][0], ah[ms][1], ah[ms][2], ah[ms][3],
                             bh[j][0], bh[j][1]);
                    mma_tf32(c[ms][j], al[ms][0], al[ms][1], al[ms][2], al[ms][3],
                             bh[j][0], bh[j][1]);
                    mma_tf32(c[ms][j], ah[ms][0], ah[ms][1], ah[ms][2], ah[ms][3],
                             bl[j][0], bl[j][1]);
                }
        }
        if (k < 4) {
            __syncthreads();
            fillW(k + 1);
            CP_COMMIT(); CP_WAIT0();
            __syncthreads();
        }
    }
    __syncthreads();

    float* convS = xf;
#pragma unroll
    for (int ms = 0; ms < 2; ++ms)
#pragma unroll
        for (int j = 0; j < 4; ++j) {
            int row = mw * 32 + ms * 16 + (lane >> 2);
            int col = nw * 32 + j * 8 + 2 * (lane & 3);
            convS[row * 68 + col]           = c[ms][j][0];
            convS[row * 68 + col + 1]       = c[ms][j][1];
            convS[(row + 8) * 68 + col]     = c[ms][j][2];
            convS[(row + 8) * 68 + col + 1] = c[ms][j][3];
        }
    __syncthreads();
    for (int idx = tid; idx < 42 * 64; idx += 256) {
        int oc = idx & 63, pl = idx >> 6;
        int p = bx * 42 + pl;
        if (p < L2P) {
            float sc = scS[oc], sh = shS[oc];
            float y0 = fmaf(convS[(3 * pl) * 68 + oc],     sc, sh);
            float y1 = fmaf(convS[(3 * pl + 1) * 68 + oc], sc, sh);
            float y2 = fmaf(convS[(3 * pl + 2) * 68 + oc], sc, sh);
            g_h2T[(b * L2P + p) * C2 + oc] = fmaxf(fmaxf(fmaxf(y0, y1), y2), 0.f);
        }
    }
}

// ============================================================
// Kernel 3: conv3 via mma.sync tf32 3x-split implicit GEMM
// M=128 conv rows (63 pooled, overlap tiles), N=64, K=64 x 3 taps.
// X tile 131x64 (stride 68) + all W taps resident. grid (3, 256).
// ============================================================
#define CV3_SMEM ((131 * 68 + 192 * 68 + 128) * 4)   // 88,368 B

__global__ void __launch_bounds__(256, 2) k_conv3mma(
        const float* __restrict__ bias,
        const float* __restrict__ bng,
        const float* __restrict__ bnb,
        const float* __restrict__ bnm,
        const float* __restrict__ bnv) {
    extern __shared__ float sm[];
    float* xf  = sm;                       // [131][68]
    float* wf  = sm + 131 * 68;            // [192][68]  (k*64+oc rows)
    float* scS = sm + 131 * 68 + 192 * 68; // [64]
    float* shS = scS + 64;

    const int b    = blockIdx.y;
    const int bx   = blockIdx.x;
    const int ct0  = bx * 126;
    const int tid  = threadIdx.x;
    const int lane = tid & 31;
    const int wid  = tid >> 5;
    const int mw   = wid & 3;
    const int nw   = wid >> 2;

    if (tid < 64) {
        float sc = bng[tid] * rsqrtf(bnv[tid] + EPS_BN);
        scS[tid] = sc;
        shS[tid] = bnb[tid] + (bias[tid] - bnm[tid]) * sc;
    }

    // stage X: 131 rows x 64 ic
    for (int idx = tid; idx < 131 * 16; idx += 256) {
        int j = idx >> 4, icq = idx & 15;
        int t = ct0 + j;
        float* dst = xf + j * 68 + icq * 4;
        if (t < L2P) cpa16(dst, &g_h2T[(b * L2P + t) * C2 + icq * 4]);
        else { dst[0] = 0.f; dst[1] = 0.f; dst[2] = 0.f; dst[3] = 0.f; }
    }
    // stage all W taps: 192 rows x 64 ic
    for (int idx = tid; idx < 192 * 16; idx += 256) {
        int row = idx >> 4, icq = idx & 15;
        cpa16(wf + row * 68 + icq * 4, g_w3T + row * 64 + icq * 4);
    }
    CP_COMMIT(); CP_WAIT0();
    __syncthreads();

    float c[2][4][4];
#pragma unroll
    for (int ms = 0; ms < 2; ++ms)
#pragma unroll
        for (int j = 0; j < 4; ++j)
#pragma unroll
            for (int q = 0; q < 4; ++q) c[ms][j][q] = 0.f;

#pragma unroll 1
    for (int k = 0; k < 3; ++k) {
        const float* xfp = xf + (mw * 32 + (lane >> 2) + k) * 68 + (lane & 3);
        const float* wfp = wf + (k * 64 + nw * 32 + (lane >> 2)) * 68 + (lane & 3);
#pragma unroll 2
        for (int ks = 0; ks < 8; ++ks) {
            const int kb = ks * 8;
            unsigned ah[2][4], al[2][4], bh[4][2], bl[4][2];
#pragma unroll
            for (int ms = 0; ms < 2; ++ms) {
                int base = ms * 16 * 68 + kb;
                tfsplit(xfp[base],              ah[ms][0], al[ms][0]);
                tfsplit(xfp[base + 8 * 68],     ah[ms][1], al[ms][1]);
                tfsplit(xfp[base + 4],          ah[ms][2], al[ms][2]);
                tfsplit(xfp[base + 8 * 68 + 4], ah[ms][3], al[ms][3]);
            }
#pragma unroll
            for (int j = 0; j < 4; ++j) {
                int base = j * 8 * 68 + kb;
                tfsplit(wfp[base],     bh[j][0], bl[j][0]);
                tfsplit(wfp[base + 4], bh[j][1], bl[j][1]);
            }
#pragma unroll
            for (int ms = 0; ms < 2; ++ms)
#pragma unroll
                for (int j = 0; j < 4; ++j) {
                    mma_tf32(c[ms][j], ah[ms][0], ah[ms][1], ah[ms][2], ah[ms][3],
                             bh[j][0], bh[j][1]);
                    mma_tf32(c[ms][j], al[ms][0], al[ms][1], al[ms][2], al[ms][3],
                             bh[j][0], bh[j][1]);
                    mma_tf32(c[ms][j], ah[ms][0], ah[ms][1], ah[ms][2], ah[ms][3],
                             bl[j][0], bl[j][1]);
                }
        }
    }
    __syncthreads();

    float* convS = xf;   // [128][68]
#pragma unroll
    for (int ms = 0; ms < 2; ++ms)
#pragma unroll
        for (int j = 0; j < 4; ++j) {
            int row = mw * 32 + ms * 16 + (lane >> 2);
            int col = nw * 32 + j * 8 + 2 * (lane & 3);
            convS[row * 68 + col]           = c[ms][j][0];
            convS[row * 68 + col + 1]       = c[ms][j][1];
            convS[(row + 8) * 68 + col]     = c[ms][j][2];
            convS[(row + 8) * 68 + col + 1] = c[ms][j][3];
        }
    __syncthreads();
    for (int idx = tid; idx < 63 * 64; idx += 256) {
        int oc = idx & 63, pl = idx >> 6;
        int p = bx * 63 + pl;
        if (p < L3P) {
            float sc = scS[oc], sh = shS[oc];
            float y0 = fmaf(convS[(2 * pl) * 68 + oc],     sc, sh);
            float y1 = fmaf(convS[(2 * pl + 1) * 68 + oc], sc, sh);
            float y2 = fmaf(convS[(2 * pl + 2) * 68 + oc], sc, sh);
            float y = fmaxf(fmaxf(fmaxf(y0, y1), y2), 0.f);
            g_h3T[(oc * L3P + p) * BATCH + b] = y;
        }
    }
}

// ============================================================
// Kernel 4a: fc1 split-K. 256 blocks x 42-wide K chunks.
// ============================================================
__global__ void __launch_bounds__(256) k_fcA(const float* __restrict__ fc1w) {
    const int chunk = blockIdx.x;
    const int r = threadIdx.x;
    __shared__ float wsS[42][48];

    for (int idx = r; idx < 42 * 48; idx += 256) {
        int o = idx / 42, k = idx % 42;
        wsS[k][o] = fc1w[o * FCIN + chunk * 42 + k];
    }
    __syncthreads();

    ull acc[24];
#pragma unroll
    for (int p = 0; p < 24; ++p) acc[p] = 0ull;

#pragma unroll 2
    for (int k = 0; k < 42; ++k) {
        float xv = g_h3T[(chunk * 42 + k) * BATCH + r];
        ull xd = dup2(xv);
#pragma unroll
        for (int p = 0; p < 24; ++p)
            fma2(acc[p], *(const ull*)&wsS[k][2 * p], xd);
    }
    float* outp = &g_part[(chunk * BATCH + r) * 48];
#pragma unroll
    for (int p = 0; p < 24; ++p) {
        outp[2 * p]     = lo32(acc[p]);
        outp[2 * p + 1] = hi32(acc[p]);
    }
}

// ============================================================
// Kernel 4b: reduce + fc2/fc3/fc4 + tanh
// ============================================================
__global__ void k_fcB(const float* __restrict__ fc1b,
                      const float* __restrict__ fc2w, const float* __restrict__ fc2b,
                      const float* __restrict__ fc3w, const float* __restrict__ fc3b,
                      const float* __restrict__ fc4w, const float* __restrict__ fc4b) {
    const int r = blockIdx.x;
    const int t = threadIdx.x;
    __shared__ float s1[48], s2[32], s3[16];

    if (t < 48) {
        float a = 0.f;
#pragma unroll 8
        for (int c = 0; c < 256; ++c)
            a += g_part[(c * BATCH + r) * 48 + t];
        s1[t] = fmaxf(a + fc1b[t], 0.f);
    }
    __syncthreads();
    if (t < 32) {
        float a2 = 0.f;
#pragma unroll
        for (int k = 0; k < 48; ++k) a2 = fmaf(s1[k], fc2w[t * 48 + k], a2);
        s2[t] = fmaxf(a2 + fc2b[t], 0.f);
    }
    __syncthreads();
    if (t < 16) {
        float a3 = 0.f;
#pragma unroll
        for (int k = 0; k < 32; ++k) a3 = fmaf(s2[k], fc3w[t * 32 + k], a3);
        s3[t] = fmaxf(a3 + fc3b[t], 0.f);
    }
    __syncthreads();
    if (t < 5) {
        float a4 = 0.f;
#pragma unroll
        for (int k = 0; k < 16; ++k) a4 = fmaf(s3[k], fc4w[t * 16 + k], a4);
        g_theta[r * 5 + t] = tanhf(a4 + fc4b[t]);
    }
}

// ============================================================
// Kernel 5: CPAB integrate + resample
// ============================================================
__global__ void k_warp(const float* __restrict__ x,
                       const float* __restrict__ basis,
                       float* __restrict__ out) {
    const int b   = blockIdx.x;
    const int tid = threadIdx.x;
    __shared__ float sa[6], sb[6];
    if (tid < 12) {
        float a = 0.f;
#pragma unroll
        for (int k = 0; k < 5; ++k)
            a = fmaf(g_theta[b * 5 + k], basis[tid * 5 + k], a);
        if (tid & 1) sb[tid >> 1] = a; else sa[tid >> 1] = a;
    }
    __syncthreads();
    float la[6], lb[6];
#pragma unroll
    for (int c = 0; c < 6; ++c) { la[c] = sa[c]; lb[c] = sb[c]; }
    const float INF = __int_as_float(0x7f800000);

    for (int r = 0; r < 8; ++r) {
        int i = tid + r * 256;
        float xv = (float)i / 2047.0f;
        float t = 1.0f;
#pragma unroll 1
        for (int it = 0; it < 7; ++it) {
            int c = (int)floorf(xv * 6.0f);
            c = c < 0 ? 0 : (c > 5 ? 5 : c);
            float a  = la[c];
            float bc = lb[c];
            float v  = fmaf(a, xv, bc);
            float xb = (v >= 0.f) ? (float)(c + 1) / 6.0f : (float)c / 6.0f;
            bool  big = fabsf(a) > 1e-8f;
            float a_s = big ? a : 1.0f;
            float boa = bc / a_s;
            float z   = xv + boa;
            float zb  = xb + boa;
            float zden  = (fabsf(z) > 1e-12f) ? z : 1e-12f;
            float ratio = zb / zden;
            float t_exp = logf(fmaxf(ratio, 1e-12f)) / a_s;
            float v_s   = (fabsf(v) > 1e-12f) ? v : 1.0f;
            float t_lin = (xb - xv) / v_s;
            float thit  = big ? t_exp : t_lin;
            bool valid = (fabsf(v) > 1e-12f) && (thit > 0.f) &&
                         ((big ? ratio : 1.0f) > 0.f);
            thit = valid ? thit : INF;
            float tau = fminf(t, thit);
            float x_new = big ? (z * expf(a * tau) - (z - xv))
                              : fmaf(bc, tau, xv);
            bool hit = (thit <= t);
            float nudge = (v >= 0.f) ? 1e-6f : -1e-6f;
            xv = hit ? (xb + nudge) : x_new;
            xv = fminf(fmaxf(xv, 0.f), 1.f);
            t = fmaxf(t - tau, 0.f);
        }
        float p = fminf(fmaxf(xv, 0.f), 1.f) * 2047.0f;
        int x0 = (int)floorf(p);
        x0 = x0 < 0 ? 0 : (x0 > 2046 ? 2046 : x0);
        float wgt = p - (float)x0;
#pragma unroll
        for (int ch = 0; ch < 3; ++ch) {
            float d0 = x[(b * 3 + ch) * SIGLEN + x0];
            float d1 = x[(b * 3 + ch) * SIGLEN + x0 + 1];
            out[(b * 3 + ch) * SIGLEN + i] = d0 * (1.0f - wgt) + d1 * wgt;
        }
    }
}

// ============================================================
extern "C" void kernel_launch(void* const* d_in, const int* in_sizes, int n_in,
                              void* d_out, int out_size) {
    const float* x     = (const float*)d_in[0];
    const float* c1w   = (const float*)d_in[1];
    const float* c1b   = (const float*)d_in[2];
    const float* bn1g  = (const float*)d_in[3];
    const float* bn1b  = (const float*)d_in[4];
    const float* bn1m  = (const float*)d_in[5];
    const float* bn1v  = (const float*)d_in[6];
    const float* c2w   = (const float*)d_in[7];
    const float* c2b   = (const float*)d_in[8];
    const float* bn2g  = (const float*)d_in[9];
    const float* bn2b  = (const float*)d_in[10];
    const float* bn2m  = (const float*)d_in[11];
    const float* bn2v  = (const float*)d_in[12];
    const float* c3w   = (const float*)d_in[13];
    const float* c3b   = (const float*)d_in[14];
    const float* bn3g  = (const float*)d_in[15];
    const float* bn3b  = (const float*)d_in[16];
    const float* bn3m  = (const float*)d_in[17];
    const float* bn3v  = (const float*)d_in[18];
    const float* fc1w  = (const float*)d_in[19];
    const float* fc1b  = (const float*)d_in[20];
    const float* fc2w  = (const float*)d_in[21];
    const float* fc2b  = (const float*)d_in[22];
    const float* fc3w  = (const float*)d_in[23];
    const float* fc3b  = (const float*)d_in[24];
    const float* fc4w  = (const float*)d_in[25];
    const float* fc4b  = (const float*)d_in[26];
    const float* basis = (const float*)d_in[27];
    float* out = (float*)d_out;

    static int attr_done = 0;
    if (!attr_done) {
        cudaFuncSetAttribute(k_conv2mma,
                             cudaFuncAttributeMaxDynamicSharedMemorySize, CV2_SMEM);
        cudaFuncSetAttribute(k_conv3mma,
                             cudaFuncAttributeMaxDynamicSharedMemorySize, CV3_SMEM);
        attr_done = 1;
    }

    k_prep<<<160, 256>>>(c2w, c3w);
    dim3 g1(16, BATCH);  k_conv1<<<g1, 128>>>(x, c1w, c1b, bn1g, bn1b, bn1m, bn1v);
    dim3 g2(9,  BATCH);  k_conv2mma<<<g2, 256, CV2_SMEM>>>(c2b, bn2g, bn2b, bn2m, bn2v);
    dim3 g3(3,  BATCH);  k_conv3mma<<<g3, 256, CV3_SMEM>>>(c3b, bn3g, bn3b, bn3m, bn3v);
    k_fcA<<<256, 256>>>(fc1w);
    k_fcB<<<BATCH, 64>>>(fc1b, fc2w, fc2b, fc3w, fc3b, fc4w, fc4b);
    k_warp<<<BATCH, 256>>>(x, basis, out);
}

// round 12
// speedup vs baseline: 1.7353x; 1.0263x over previous
#include <cuda_runtime.h>
#include <math.h>
#include <stdint.h>

#define BATCH 256
#define SIGLEN 2048
#define L1P 1022
#define L2P 339
#define L3P 168
#define C1 128
#define C2 64
#define C3 64
#define FCIN 10752
#define EPS_BN 1e-5f

typedef unsigned long long ull;

// ---- scratch ----
__device__ float g_h1T[BATCH * L1P * C1];   // [b][pos][ic]
__device__ float g_h2T[BATCH * L2P * C2];   // [b][pos][oc]
__device__ float g_h3T[FCIN * BATCH];       // [feature][batch]
__device__ float g_w2T[5 * 64 * 128];       // [k][oc][ic]
__device__ float g_w3T[3 * 64 * 64];        // [k][oc][ic]
__device__ float g_part[256 * BATCH * 48];
__device__ float g_theta[BATCH * 5];

__device__ __forceinline__ void fma2(ull& d, ull a, ull b) {
    asm("fma.rn.f32x2 %0, %1, %2, %0;" : "+l"(d) : "l"(a), "l"(b));
}
__device__ __forceinline__ ull dup2(float v) {
    ull r; asm("mov.b64 %0, {%1, %1};" : "=l"(r) : "f"(v)); return r;
}
__device__ __forceinline__ float lo32(ull v) { return __uint_as_float((unsigned)v); }
__device__ __forceinline__ float hi32(ull v) { return __uint_as_float((unsigned)(v >> 32)); }

__device__ __forceinline__ void cpa16(void* dst, const void* src) {
    unsigned d = (unsigned)__cvta_generic_to_shared(dst);
    asm volatile("cp.async.cg.shared.global [%0], [%1], 16;" :: "r"(d), "l"(src));
}
#define CP_COMMIT()  asm volatile("cp.async.commit_group;" ::: "memory")
#define CP_WAIT0()   asm volatile("cp.async.wait_group 0;" ::: "memory")

__device__ __forceinline__ float f2tf_f(float v) {
    unsigned r; asm("cvt.rna.tf32.f32 %0, %1;" : "=r"(r) : "f"(v));
    return __uint_as_float(r);
}
__device__ __forceinline__ void tfsplit(float v, unsigned& h, unsigned& l) {
    float hf = f2tf_f(v);
    h = __float_as_uint(hf);
    l = __float_as_uint(f2tf_f(v - hf));
}
__device__ __forceinline__ void mma_tf32(float* d,
        unsigned a0, unsigned a1, unsigned a2, unsigned a3,
        unsigned b0, unsigned b1) {
    asm("mma.sync.aligned.m16n8k8.row.col.f32.tf32.tf32.f32 "
        "{%0,%1,%2,%3}, {%4,%5,%6,%7}, {%8,%9}, {%0,%1,%2,%3};"
        : "+f"(d[0]), "+f"(d[1]), "+f"(d[2]), "+f"(d[3])
        : "r"(a0), "r"(a1), "r"(a2), "r"(a3), "r"(b0), "r"(b1));
}

// ============================================================
// Kernel 0: weight transposes
// ============================================================
__global__ void k_prep(const float* __restrict__ w2, const float* __restrict__ w3) {
    int i = blockIdx.x * blockDim.x + threadIdx.x;
    if (i < 5 * 64 * 128) {
        int k = i >> 13, oc = (i >> 7) & 63, ic = i & 127;
        g_w2T[i] = w2[oc * 640 + ic * 5 + k];
    }
    if (i < 3 * 64 * 64) {
        int k = i >> 12, oc = (i >> 6) & 63, ic = i & 63;
        g_w3T[i] = w3[oc * 192 + ic * 3 + k];
    }
}

// ============================================================
// Kernel 1: conv1 (3->128, k3) + BN + pool(3,2) + relu -> g_h1T[b][pos][ic]
// f32x2 conv-pairs with rolling pool window: per pooled output
// 9 LDS.64 + 9 fma2 (pair shared with neighbor).
// ============================================================
__global__ void __launch_bounds__(128) k_conv1(
        const float* __restrict__ x,
        const float* __restrict__ w,
        const float* __restrict__ bias,
        const float* __restrict__ bng,
        const float* __restrict__ bnb,
        const float* __restrict__ bnm,
        const float* __restrict__ bnv) {
    const int b  = blockIdx.y;
    const int p0 = blockIdx.x * 64;
    const int oc = threadIdx.x;
    __shared__ float2 xs2[3][132];   // xs2[ch][j] = (x[t0+j], x[t0+j+1])
    __shared__ float outS[64][128];

    const int t0 = 2 * p0;
    for (int idx = threadIdx.x; idx < 3 * 131; idx += 128) {
        int ch = idx / 131, j = idx % 131;
        int t = t0 + j;
        const float* xc = x + (b * 3 + ch) * SIGLEN;
        float v0 = (t < SIGLEN) ? xc[t] : 0.f;
        float v1 = (t + 1 < SIGLEN) ? xc[t + 1] : 0.f;
        xs2[ch][j] = make_float2(v0, v1);
    }
    ull wd[9];
#pragma unroll
    for (int j = 0; j < 9; ++j) wd[j] = dup2(w[oc * 9 + j]);
    float scale = bng[oc] / sqrtf(bnv[oc] + EPS_BN);
    float shift = bnb[oc] + (bias[oc] - bnm[oc]) * scale;
    __syncthreads();

    // pair i = (conv(2i), conv(2i+1)) local
    auto cpair = [&](int i) {
        ull a = 0ull;
#pragma unroll
        for (int ch = 0; ch < 3; ++ch)
#pragma unroll
            for (int k = 0; k < 3; ++k)
                fma2(a, wd[ch * 3 + k], *(const ull*)&xs2[ch][2 * i + k]);
        return a;
    };

    ull prev = cpair(0);
#pragma unroll 4
    for (int pl = 0; pl < 64; ++pl) {
        ull nxt = cpair(pl + 1);
        float y0 = fmaf(lo32(prev), scale, shift);
        float y1 = fmaf(hi32(prev), scale, shift);
        float y2 = fmaf(lo32(nxt),  scale, shift);
        outS[pl][oc] = fmaxf(fmaxf(fmaxf(y0, y1), y2), 0.f);
        prev = nxt;
    }
    __syncthreads();
    for (int idx = threadIdx.x; idx < 64 * 128; idx += 128) {
        int pl = idx >> 7, col = idx & 127;
        int p = p0 + pl;
        if (p < L1P) g_h1T[(b * L1P + p) * C1 + col] = outS[pl][col];
    }
}

// ============================================================
// Kernel 2: conv2 via mma.sync tf32 3x-split implicit GEMM  [HOT]
// (R10/R11 proven version, untouched)
// ============================================================
#define CV2_SMEM ((17424 + 8448 + 128) * 4)   // 104,000 B

__global__ void __launch_bounds__(256, 2) k_conv2mma(
        const float* __restrict__ bias,
        const float* __restrict__ bng,
        const float* __restrict__ bnb,
        const float* __restrict__ bnm,
        const float* __restrict__ bnv) {
    extern __shared__ float sm[];
    float* xf  = sm;               // [132][132] f32
    float* wf  = sm + 17424;       // [64][132]  f32
    float* scS = sm + 25872;       // [64]
    float* shS = sm + 25936;       // [64]

    const int b    = blockIdx.y;
    const int bx   = blockIdx.x;
    const int ct0  = bx * 126;
    const int tid  = threadIdx.x;
    const int lane = tid & 31;
    const int wid  = tid >> 5;
    const int mw   = wid & 3;
    const int nw   = wid >> 2;

    if (tid < 64) {
        float sc = bng[tid] * rsqrtf(bnv[tid] + EPS_BN);
        scS[tid] = sc;
        shS[tid] = bnb[tid] + (bias[tid] - bnm[tid]) * sc;
    }

    const float* h1b = &g_h1T[(size_t)b * L1P * C1];
    for (int idx = tid; idx < 132 * 32; idx += 256) {
        int j = idx >> 5, icq = idx & 31;
        int t = ct0 + j;
        float* dst = xf + j * 132 + icq * 4;
        if (t < L1P) cpa16(dst, h1b + (size_t)t * C1 + icq * 4);
        else { dst[0] = 0.f; dst[1] = 0.f; dst[2] = 0.f; dst[3] = 0.f; }
    }
    auto fillW = [&](int k) {
        for (int idx = tid; idx < 64 * 32; idx += 256) {
            int oc = idx >> 5, icq = idx & 31;
            cpa16(wf + oc * 132 + icq * 4, g_w2T + (k * 64 + oc) * 128 + icq * 4);
        }
    };
    fillW(0);
    CP_COMMIT(); CP_WAIT0();
    __syncthreads();

    float c[2][4][4];
#pragma unroll
    for (int ms = 0; ms < 2; ++ms)
#pragma unroll
        for (int j = 0; j < 4; ++j)
#pragma unroll
            for (int q = 0; q < 4; ++q) c[ms][j][q] = 0.f;

    for (int k = 0; k < 5; ++k) {
        const float* xfp = xf + (mw * 32 + (lane >> 2) + k) * 132 + (lane & 3);
        const float* wfp = wf + (nw * 32 + (lane >> 2)) * 132 + (lane & 3);
#pragma unroll 2
        for (int ks = 0; ks < 16; ++ks) {
            const int kb = ks * 8;
            unsigned ah[2][4], al[2][4], bh[4][2], bl[4][2];
#pragma unroll
            for (int ms = 0; ms < 2; ++ms) {
                int base = ms * 16 * 132 + kb;
                tfsplit(xfp[base],               ah[ms][0], al[ms][0]);
                tfsplit(xfp[base + 8 * 132],     ah[ms][1], al[ms][1]);
                tfsplit(xfp[base + 4],           ah[ms][2], al[ms][2]);
                tfsplit(xfp[base + 8 * 132 + 4], ah[ms][3], al[ms][3]);
            }
#pragma unroll
            for (int j = 0; j < 4; ++j) {
                int base = j * 8 * 132 + kb;
                tfsplit(wfp[base],     bh[j][0], bl[j][0]);
                tfsplit(wfp[base + 4], bh[j][1], bl[j][1]);
            }
#pragma unroll
            for (int ms = 0; ms < 2; ++ms)
#pragma unroll
                for (int j = 0; j < 4; ++j) {
                    mma_tf32(c[ms][j], ah[ms][0], ah[ms][1], ah[ms][2], ah[ms][3],
                             bh[j][0], bh[j][1]);
                    mma_tf32(c[ms][j], al[ms][0], al[ms][1], al[ms][2], al[ms][3],
                             bh[j][0], bh[j][1]);
                    mma_tf32(c[ms][j], ah[ms][0], ah[ms][1], ah[ms][2], ah[ms][3],
                             bl[j][0], bl[j][1]);
                }
        }
        if (k < 4) {
            __syncthreads();
            fillW(k + 1);
            CP_COMMIT(); CP_WAIT0();
            __syncthreads();
        }
    }
    __syncthreads();

    float* convS = xf;
#pragma unroll
    for (int ms = 0; ms < 2; ++ms)
#pragma unroll
        for (int j = 0; j < 4; ++j) {
            int row = mw * 32 + ms * 16 + (lane >> 2);
            int col = nw * 32 + j * 8 + 2 * (lane & 3);
            convS[row * 68 + col]           = c[ms][j][0];
            convS[row * 68 + col + 1]       = c[ms][j][1];
            convS[(row + 8) * 68 + col]     = c[ms][j][2];
            convS[(row + 8) * 68 + col + 1] = c[ms][j][3];
        }
    __syncthreads();
    for (int idx = tid; idx < 42 * 64; idx += 256) {
        int oc = idx & 63, pl = idx >> 6;
        int p = bx * 42 + pl;
        if (p < L2P) {
            float sc = scS[oc], sh = shS[oc];
            float y0 = fmaf(convS[(3 * pl) * 68 + oc],     sc, sh);
            float y1 = fmaf(convS[(3 * pl + 1) * 68 + oc], sc, sh);
            float y2 = fmaf(convS[(3 * pl + 2) * 68 + oc], sc, sh);
            g_h2T[(b * L2P + p) * C2 + oc] = fmaxf(fmaxf(fmaxf(y0, y1), y2), 0.f);
        }
    }
}

// ============================================================
// Kernel 3: conv3 via mma.sync tf32 3x-split implicit GEMM
// (R11 proven version, untouched)
// ============================================================
#define CV3_SMEM ((131 * 68 + 192 * 68 + 128) * 4)   // 88,368 B

__global__ void __launch_bounds__(256, 2) k_conv3mma(
        const float* __restrict__ bias,
        const float* __restrict__ bng,
        const float* __restrict__ bnb,
        const float* __restrict__ bnm,
        const float* __restrict__ bnv) {
    extern __shared__ float sm[];
    float* xf  = sm;                       // [131][68]
    float* wf  = sm + 131 * 68;            // [192][68]
    float* scS = sm + 131 * 68 + 192 * 68; // [64]
    float* shS = scS + 64;

    const int b    = blockIdx.y;
    const int bx   = blockIdx.x;
    const int ct0  = bx * 126;
    const int tid  = threadIdx.x;
    const int lane = tid & 31;
    const int wid  = tid >> 5;
    const int mw   = wid & 3;
    const int nw   = wid >> 2;

    if (tid < 64) {
        float sc = bng[tid] * rsqrtf(bnv[tid] + EPS_BN);
        scS[tid] = sc;
        shS[tid] = bnb[tid] + (bias[tid] - bnm[tid]) * sc;
    }

    for (int idx = tid; idx < 131 * 16; idx += 256) {
        int j = idx >> 4, icq = idx & 15;
        int t = ct0 + j;
        float* dst = xf + j * 68 + icq * 4;
        if (t < L2P) cpa16(dst, &g_h2T[(b * L2P + t) * C2 + icq * 4]);
        else { dst[0] = 0.f; dst[1] = 0.f; dst[2] = 0.f; dst[3] = 0.f; }
    }
    for (int idx = tid; idx < 192 * 16; idx += 256) {
        int row = idx >> 4, icq = idx & 15;
        cpa16(wf + row * 68 + icq * 4, g_w3T + row * 64 + icq * 4);
    }
    CP_COMMIT(); CP_WAIT0();
    __syncthreads();

    float c[2][4][4];
#pragma unroll
    for (int ms = 0; ms < 2; ++ms)
#pragma unroll
        for (int j = 0; j < 4; ++j)
#pragma unroll
            for (int q = 0; q < 4; ++q) c[ms][j][q] = 0.f;

#pragma unroll 1
    for (int k = 0; k < 3; ++k) {
        const float* xfp = xf + (mw * 32 + (lane >> 2) + k) * 68 + (lane & 3);
        const float* wfp = wf + (k * 64 + nw * 32 + (lane >> 2)) * 68 + (lane & 3);
#pragma unroll 2
        for (int ks = 0; ks < 8; ++ks) {
            const int kb = ks * 8;
            unsigned ah[2][4], al[2][4], bh[4][2], bl[4][2];
#pragma unroll
            for (int ms = 0; ms < 2; ++ms) {
                int base = ms * 16 * 68 + kb;
                tfsplit(xfp[base],              ah[ms][0], al[ms][0]);
                tfsplit(xfp[base + 8 * 68],     ah[ms][1], al[ms][1]);
                tfsplit(xfp[base + 4],          ah[ms][2], al[ms][2]);
                tfsplit(xfp[base + 8 * 68 + 4], ah[ms][3], al[ms][3]);
            }
#pragma unroll
            for (int j = 0; j < 4; ++j) {
                int base = j * 8 * 68 + kb;
                tfsplit(wfp[base],     bh[j][0], bl[j][0]);
                tfsplit(wfp[base + 4], bh[j][1], bl[j][1]);
            }
#pragma unroll
            for (int ms = 0; ms < 2; ++ms)
#pragma unroll
                for (int j = 0; j < 4; ++j) {
                    mma_tf32(c[ms][j], ah[ms][0], ah[ms][1], ah[ms][2], ah[ms][3],
                             bh[j][0], bh[j][1]);
                    mma_tf32(c[ms][j], al[ms][0], al[ms][1], al[ms][2], al[ms][3],
                             bh[j][0], bh[j][1]);
                    mma_tf32(c[ms][j], ah[ms][0], ah[ms][1], ah[ms][2], ah[ms][3],
                             bl[j][0], bl[j][1]);
                }
        }
    }
    __syncthreads();

    float* convS = xf;   // [128][68]
#pragma unroll
    for (int ms = 0; ms < 2; ++ms)
#pragma unroll
        for (int j = 0; j < 4; ++j) {
            int row = mw * 32 + ms * 16 + (lane >> 2);
            int col = nw * 32 + j * 8 + 2 * (lane & 3);
            convS[row * 68 + col]           = c[ms][j][0];
            convS[row * 68 + col + 1]       = c[ms][j][1];
            convS[(row + 8) * 68 + col]     = c[ms][j][2];
            convS[(row + 8) * 68 + col + 1] = c[ms][j][3];
        }
    __syncthreads();
    for (int idx = tid; idx < 63 * 64; idx += 256) {
        int oc = idx & 63, pl = idx >> 6;
        int p = bx * 63 + pl;
        if (p < L3P) {
            float sc = scS[oc], sh = shS[oc];
            float y0 = fmaf(convS[(2 * pl) * 68 + oc],     sc, sh);
            float y1 = fmaf(convS[(2 * pl + 1) * 68 + oc], sc, sh);
            float y2 = fmaf(convS[(2 * pl + 2) * 68 + oc], sc, sh);
            float y = fmaxf(fmaxf(fmaxf(y0, y1), y2), 0.f);
            g_h3T[(oc * L3P + p) * BATCH + b] = y;
        }
    }
}

// ============================================================
// Kernel 4a: fc1 split-K, x-slab staged in smem (no LDG stalls).
// 256 blocks x 42-wide K chunks.
// ============================================================
#define FCA_SMEM ((2016 + 10752) * 4)   // 51,072 B

__global__ void __launch_bounds__(256) k_fcA(const float* __restrict__ fc1w) {
    extern __shared__ float sm[];
    float* wsS = sm;           // [42][48]
    float* xS  = sm + 2016;    // [42][256]

    const int chunk = blockIdx.x;
    const int r = threadIdx.x;

    for (int idx = r; idx < 42 * 48; idx += 256) {
        int o = idx / 42, k = idx % 42;
        wsS[k * 48 + o] = fc1w[o * FCIN + chunk * 42 + k];
    }
    for (int i = r * 4; i < 10752; i += 1024)
        cpa16(xS + i, g_h3T + (size_t)chunk * 10752 + i);
    CP_COMMIT(); CP_WAIT0();
    __syncthreads();

    ull acc[24];
#pragma unroll
    for (int p = 0; p < 24; ++p) acc[p] = 0ull;

#pragma unroll 2
    for (int k = 0; k < 42; ++k) {
        ull xd = dup2(xS[k * 256 + r]);
#pragma unroll
        for (int p = 0; p < 24; ++p)
            fma2(acc[p], *(const ull*)&wsS[k * 48 + 2 * p], xd);
    }
    float* outp = &g_part[(chunk * BATCH + r) * 48];
#pragma unroll
    for (int p = 0; p < 24; ++p) {
        outp[2 * p]     = lo32(acc[p]);
        outp[2 * p + 1] = hi32(acc[p]);
    }
}

// ============================================================
// Kernel 4b: reduce (parallelized) + fc2/fc3/fc4 + tanh
// ============================================================
__global__ void __launch_bounds__(256) k_fcB(
        const float* __restrict__ fc1b,
        const float* __restrict__ fc2w, const float* __restrict__ fc2b,
        const float* __restrict__ fc3w, const float* __restrict__ fc3b,
        const float* __restrict__ fc4w, const float* __restrict__ fc4b) {
    const int r = blockIdx.x;
    const int tid = threadIdx.x;
    const int t = tid % 48, g = tid / 48;   // g 0..4 active (240 threads)
    __shared__ float part[5][48];
    __shared__ float s1[48], s2[32], s3[16];

    if (g < 5) {
        int c0 = g * 52;
        int c1 = (c0 + 52 < 256) ? c0 + 52 : 256;
        float a = 0.f;
        for (int c = c0; c < c1; ++c)
            a += g_part[(c * BATCH + r) * 48 + t];
        part[g][t] = a;
    }
    __syncthreads();
    if (tid < 48) {
        float a = part[0][tid] + part[1][tid] + part[2][tid]
                + part[3][tid] + part[4][tid];
        s1[tid] = fmaxf(a + fc1b[tid], 0.f);
    }
    __syncthreads();
    if (tid < 32) {
        float a2 = 0.f;
#pragma unroll
        for (int k = 0; k < 48; ++k) a2 = fmaf(s1[k], fc2w[tid * 48 + k], a2);
        s2[tid] = fmaxf(a2 + fc2b[tid], 0.f);
    }
    __syncthreads();
    if (tid < 16) {
        float a3 = 0.f;
#pragma unroll
        for (int k = 0; k < 32; ++k) a3 = fmaf(s2[k], fc3w[tid * 32 + k], a3);
        s3[tid] = fmaxf(a3 + fc3b[tid], 0.f);
    }
    __syncthreads();
    if (tid < 5) {
        float a4 = 0.f;
#pragma unroll
        for (int k = 0; k < 16; ++k) a4 = fmaf(s3[k], fc4w[tid * 16 + k], a4);
        g_theta[r * 5 + tid] = tanhf(a4 + fc4b[tid]);
    }
}

// ============================================================
// Kernel 5: CPAB integrate + resample
// ============================================================
__global__ void k_warp(const float* __restrict__ x,
                       const float* __restrict__ basis,
                       float* __restrict__ out) {
    const int b   = blockIdx.x;
    const int tid = threadIdx.x;
    __shared__ float sa[6], sb[6];
    if (tid < 12) {
        float a = 0.f;
#pragma unroll
        for (int k = 0; k < 5; ++k)
            a = fmaf(g_theta[b * 5 + k], basis[tid * 5 + k], a);
        if (tid & 1) sb[tid >> 1] = a; else sa[tid >> 1] = a;
    }
    __syncthreads();
    float la[6], lb[6];
#pragma unroll
    for (int c = 0; c < 6; ++c) { la[c] = sa[c]; lb[c] = sb[c]; }
    const float INF = __int_as_float(0x7f800000);

    for (int r = 0; r < 8; ++r) {
        int i = tid + r * 256;
        float xv = (float)i / 2047.0f;
        float t = 1.0f;
#pragma unroll 1
        for (int it = 0; it < 7; ++it) {
            int c = (int)floorf(xv * 6.0f);
            c = c < 0 ? 0 : (c > 5 ? 5 : c);
            float a  = la[c];
            float bc = lb[c];
            float v  = fmaf(a, xv, bc);
            float xb = (v >= 0.f) ? (float)(c + 1) / 6.0f : (float)c / 6.0f;
            bool  big = fabsf(a) > 1e-8f;
            float a_s = big ? a : 1.0f;
            float boa = bc / a_s;
            float z   = xv + boa;
            float zb  = xb + boa;
            float zden  = (fabsf(z) > 1e-12f) ? z : 1e-12f;
            float ratio = zb / zden;
            float t_exp = logf(fmaxf(ratio, 1e-12f)) / a_s;
            float v_s   = (fabsf(v) > 1e-12f) ? v : 1.0f;
            float t_lin = (xb - xv) / v_s;
            float thit  = big ? t_exp : t_lin;
            bool valid = (fabsf(v) > 1e-12f) && (thit > 0.f) &&
                         ((big ? ratio : 1.0f) > 0.f);
            thit = valid ? thit : INF;
            float tau = fminf(t, thit);
            float x_new = big ? (z * expf(a * tau) - (z - xv))
                              : fmaf(bc, tau, xv);
            bool hit = (thit <= t);
            float nudge = (v >= 0.f) ? 1e-6f : -1e-6f;
            xv = hit ? (xb + nudge) : x_new;
            xv = fminf(fmaxf(xv, 0.f), 1.f);
            t = fmaxf(t - tau, 0.f);
        }
        float p = fminf(fmaxf(xv, 0.f), 1.f) * 2047.0f;
        int x0 = (int)floorf(p);
        x0 = x0 < 0 ? 0 : (x0 > 2046 ? 2046 : x0);
        float wgt = p - (float)x0;
#pragma unroll
        for (int ch = 0; ch < 3; ++ch) {
            float d0 = x[(b * 3 + ch) * SIGLEN + x0];
            float d1 = x[(b * 3 + ch) * SIGLEN + x0 + 1];
            out[(b * 3 + ch) * SIGLEN + i] = d0 * (1.0f - wgt) + d1 * wgt;
        }
    }
}

// ============================================================
extern "C" void kernel_launch(void* const* d_in, const int* in_sizes, int n_in,
                              void* d_out, int out_size) {
    const float* x     = (const float*)d_in[0];
    const float* c1w   = (const float*)d_in[1];
    const float* c1b   = (const float*)d_in[2];
    const float* bn1g  = (const float*)d_in[3];
    const float* bn1b  = (const float*)d_in[4];
    const float* bn1m  = (const float*)d_in[5];
    const float* bn1v  = (const float*)d_in[6];
    const float* c2w   = (const float*)d_in[7];
    const float* c2b   = (const float*)d_in[8];
    const float* bn2g  = (const float*)d_in[9];
    const float* bn2b  = (const float*)d_in[10];
    const float* bn2m  = (const float*)d_in[11];
    const float* bn2v  = (const float*)d_in[12];
    const float* c3w   = (const float*)d_in[13];
    const float* c3b   = (const float*)d_in[14];
    const float* bn3g  = (const float*)d_in[15];
    const float* bn3b  = (const float*)d_in[16];
    const float* bn3m  = (const float*)d_in[17];
    const float* bn3v  = (const float*)d_in[18];
    const float* fc1w  = (const float*)d_in[19];
    const float* fc1b  = (const float*)d_in[20];
    const float* fc2w  = (const float*)d_in[21];
    const float* fc2b  = (const float*)d_in[22];
    const float* fc3w  = (const float*)d_in[23];
    const float* fc3b  = (const float*)d_in[24];
    const float* fc4w  = (const float*)d_in[25];
    const float* fc4b  = (const float*)d_in[26];
    const float* basis = (const float*)d_in[27];
    float* out = (float*)d_out;

    static int attr_done = 0;
    if (!attr_done) {
        cudaFuncSetAttribute(k_conv2mma,
                             cudaFuncAttributeMaxDynamicSharedMemorySize, CV2_SMEM);
        cudaFuncSetAttribute(k_conv3mma,
                             cudaFuncAttributeMaxDynamicSharedMemorySize, CV3_SMEM);
        cudaFuncSetAttribute(k_fcA,
                             cudaFuncAttributeMaxDynamicSharedMemorySize, FCA_SMEM);
        attr_done = 1;
    }

    k_prep<<<160, 256>>>(c2w, c3w);
    dim3 g1(16, BATCH);  k_conv1<<<g1, 128>>>(x, c1w, c1b, bn1g, bn1b, bn1m, bn1v);
    dim3 g2(9,  BATCH);  k_conv2mma<<<g2, 256, CV2_SMEM>>>(c2b, bn2g, bn2b, bn2m, bn2v);
    dim3 g3(3,  BATCH);  k_conv3mma<<<g3, 256, CV3_SMEM>>>(c3b, bn3g, bn3b, bn3m, bn3v);
    k_fcA<<<256, 256, FCA_SMEM>>>(fc1w);
    k_fcB<<<BATCH, 256>>>(fc1b, fc2w, fc2b, fc3w, fc3b, fc4w, fc4b);
    k_warp<<<BATCH, 256>>>(x, basis, out);
}

// round 14
// speedup vs baseline: 1.8380x; 1.0592x over previous
#include <cuda_runtime.h>
#include <math.h>
#include <stdint.h>

#define BATCH 256
#define SIGLEN 2048
#define L1P 1022
#define L2P 339
#define L3P 168
#define C1 128
#define C2 64
#define C3 64
#define FCIN 10752
#define EPS_BN 1e-5f

typedef unsigned long long ull;

// ---- scratch ----
__device__ float g_h1T[BATCH * L1P * C1];   // [b][pos][ic]
__device__ float g_h2T[BATCH * L2P * C2];   // [b][pos][oc]
__device__ float g_h3T[FCIN * BATCH];       // [feature][batch]
__device__ float g_w2T[5 * 64 * 128];       // [k][oc][ic]
__device__ float g_w3T[3 * 64 * 64];        // [k][oc][ic]
__device__ float g_part[256 * BATCH * 48];
__device__ float g_theta[BATCH * 5];

__device__ __forceinline__ void fma2(ull& d, ull a, ull b) {
    asm("fma.rn.f32x2 %0, %1, %2, %0;" : "+l"(d) : "l"(a), "l"(b));
}
__device__ __forceinline__ ull dup2(float v) {
    ull r; asm("mov.b64 %0, {%1, %1};" : "=l"(r) : "f"(v)); return r;
}
__device__ __forceinline__ float lo32(ull v) { return __uint_as_float((unsigned)v); }
__device__ __forceinline__ float hi32(ull v) { return __uint_as_float((unsigned)(v >> 32)); }

__device__ __forceinline__ void cpa16(void* dst, const void* src) {
    unsigned d = (unsigned)__cvta_generic_to_shared(dst);
    asm volatile("cp.async.cg.shared.global [%0], [%1], 16;" :: "r"(d), "l"(src));
}
#define CP_COMMIT()  asm volatile("cp.async.commit_group;" ::: "memory")
#define CP_WAIT0()   asm volatile("cp.async.wait_group 0;" ::: "memory")

__device__ __forceinline__ float f2tf_f(float v) {
    unsigned r; asm("cvt.rna.tf32.f32 %0, %1;" : "=r"(r) : "f"(v));
    return __uint_as_float(r);
}
// hi: rounded tf32; lo: raw f32 residual (HMMA.TF32 truncates low bits itself)
__device__ __forceinline__ void tfsplit(float v, unsigned& h, unsigned& l) {
    float hf = f2tf_f(v);
    h = __float_as_uint(hf);
    l = __float_as_uint(v - hf);
}
__device__ __forceinline__ void mma_tf32(float* d,
        unsigned a0, unsigned a1, unsigned a2, unsigned a3,
        unsigned b0, unsigned b1) {
    asm("mma.sync.aligned.m16n8k8.row.col.f32.tf32.tf32.f32 "
        "{%0,%1,%2,%3}, {%4,%5,%6,%7}, {%8,%9}, {%0,%1,%2,%3};"
        : "+f"(d[0]), "+f"(d[1]), "+f"(d[2]), "+f"(d[3])
        : "r"(a0), "r"(a1), "r"(a2), "r"(a3), "r"(b0), "r"(b1));
}

// ============================================================
// Kernel 0: weight transposes
// ============================================================
__global__ void k_prep(const float* __restrict__ w2, const float* __restrict__ w3) {
    int i = blockIdx.x * blockDim.x + threadIdx.x;
    if (i < 5 * 64 * 128) {
        int k = i >> 13, oc = (i >> 7) & 63, ic = i & 127;
        g_w2T[i] = w2[oc * 640 + ic * 5 + k];
    }
    if (i < 3 * 64 * 64) {
        int k = i >> 12, oc = (i >> 6) & 63, ic = i & 63;
        g_w3T[i] = w3[oc * 192 + ic * 3 + k];
    }
}

// ============================================================
// Kernel 1: conv1 (3->128, k3) + BN + pool(3,2) + relu -> g_h1T[b][pos][ic]
// f32x2 conv-pairs, 3 parallel per-channel accumulator chains (ILP).
// ============================================================
__global__ void __launch_bounds__(128) k_conv1(
        const float* __restrict__ x,
        const float* __restrict__ w,
        const float* __restrict__ bias,
        const float* __restrict__ bng,
        const float* __restrict__ bnb,
        const float* __restrict__ bnm,
        const float* __restrict__ bnv) {
    const int b  = blockIdx.y;
    const int p0 = blockIdx.x * 64;
    const int oc = threadIdx.x;
    __shared__ float2 xs2[3][132];
    __shared__ float outS[64][128];

    const int t0 = 2 * p0;
    for (int idx = threadIdx.x; idx < 3 * 131; idx += 128) {
        int ch = idx / 131, j = idx % 131;
        int t = t0 + j;
        const float* xc = x + (b * 3 + ch) * SIGLEN;
        float v0 = (t < SIGLEN) ? xc[t] : 0.f;
        float v1 = (t + 1 < SIGLEN) ? xc[t + 1] : 0.f;
        xs2[ch][j] = make_float2(v0, v1);
    }
    ull wd[9];
#pragma unroll
    for (int j = 0; j < 9; ++j) wd[j] = dup2(w[oc * 9 + j]);
    float scale = bng[oc] / sqrtf(bnv[oc] + EPS_BN);
    float shift = bnb[oc] + (bias[oc] - bnm[oc]) * scale;
    __syncthreads();

    // pair i = (conv(2i), conv(2i+1)); 3 independent chains
    auto cpair = [&](int i) {
        ull a0 = 0ull, a1 = 0ull, a2 = 0ull;
#pragma unroll
        for (int k = 0; k < 3; ++k) {
            fma2(a0, wd[k],     *(const ull*)&xs2[0][2 * i + k]);
            fma2(a1, wd[3 + k], *(const ull*)&xs2[1][2 * i + k]);
            fma2(a2, wd[6 + k], *(const ull*)&xs2[2][2 * i + k]);
        }
        float lo = lo32(a0) + lo32(a1) + lo32(a2);
        float hi = hi32(a0) + hi32(a1) + hi32(a2);
        return make_float2(lo, hi);
    };

    float2 prev = cpair(0);
#pragma unroll 4
    for (int pl = 0; pl < 64; ++pl) {
        float2 nxt = cpair(pl + 1);
        float y0 = fmaf(prev.x, scale, shift);
        float y1 = fmaf(prev.y, scale, shift);
        float y2 = fmaf(nxt.x,  scale, shift);
        outS[pl][oc] = fmaxf(fmaxf(fmaxf(y0, y1), y2), 0.f);
        prev = nxt;
    }
    __syncthreads();
    // vectorized coalesced write-out
    for (int idx = threadIdx.x; idx < 64 * 32; idx += 128) {
        int pl = idx >> 5, q = idx & 31;
        int p = p0 + pl;
        if (p < L1P)
            *(float4*)&g_h1T[(b * L1P + p) * C1 + q * 4] =
                *(const float4*)&outS[pl][q * 4];
    }
}

// ============================================================
// Kernel 2: conv2 via mma.sync tf32 3x-split implicit GEMM  [HOT]
// ============================================================
#define CV2_SMEM ((17424 + 8448 + 128) * 4)   // 104,000 B

__global__ void __launch_bounds__(256, 2) k_conv2mma(
        const float* __restrict__ bias,
        const float* __restrict__ bng,
        const float* __restrict__ bnb,
        const float* __restrict__ bnm,
        const float* __restrict__ bnv) {
    extern __shared__ float sm[];
    float* xf  = sm;               // [132][132] f32
    float* wf  = sm + 17424;       // [64][132]  f32
    float* scS = sm + 25872;       // [64]
    float* shS = sm + 25936;       // [64]

    const int b    = blockIdx.y;
    const int bx   = blockIdx.x;
    const int ct0  = bx * 126;
    const int tid  = threadIdx.x;
    const int lane = tid & 31;
    const int wid  = tid >> 5;
    const int mw   = wid & 3;
    const int nw   = wid >> 2;

    if (tid < 64) {
        float sc = bng[tid] * rsqrtf(bnv[tid] + EPS_BN);
        scS[tid] = sc;
        shS[tid] = bnb[tid] + (bias[tid] - bnm[tid]) * sc;
    }

    const float* h1b = &g_h1T[(size_t)b * L1P * C1];
    for (int idx = tid; idx < 132 * 32; idx += 256) {
        int j = idx >> 5, icq = idx & 31;
        int t = ct0 + j;
        float* dst = xf + j * 132 + icq * 4;
        if (t < L1P) cpa16(dst, h1b + (size_t)t * C1 + icq * 4);
        else { dst[0] = 0.f; dst[1] = 0.f; dst[2] = 0.f; dst[3] = 0.f; }
    }
    auto fillW = [&](int k) {
        for (int idx = tid; idx < 64 * 32; idx += 256) {
            int oc = idx >> 5, icq = idx & 31;
            cpa16(wf + oc * 132 + icq * 4, g_w2T + (k * 64 + oc) * 128 + icq * 4);
        }
    };
    fillW(0);
    CP_COMMIT(); CP_WAIT0();
    __syncthreads();

    float c[2][4][4];
#pragma unroll
    for (int ms = 0; ms < 2; ++ms)
#pragma unroll
        for (int j = 0; j < 4; ++j)
#pragma unroll
            for (int q = 0; q < 4; ++q) c[ms][j][q] = 0.f;

    for (int k = 0; k < 5; ++k) {
        const float* xfp = xf + (mw * 32 + (lane >> 2) + k) * 132 + (lane & 3);
        const float* wfp = wf + (nw * 32 + (lane >> 2)) * 132 + (lane & 3);
#pragma unroll 2
        for (int ks = 0; ks < 16; ++ks) {
            const int kb = ks * 8;
            unsigned ah[2][4], al[2][4], bh[4][2], bl[4][2];
#pragma unroll
            for (int ms = 0; ms < 2; ++ms) {
                int base = ms * 16 * 132 + kb;
                tfsplit(xfp[base],               ah[ms][0], al[ms][0]);
                tfsplit(xfp[base + 8 * 132],     ah[ms][1], al[ms][1]);
                tfsplit(xfp[base + 4],           ah[ms][2], al[ms][2]);
                tfsplit(xfp[base + 8 * 132 + 4], ah[ms][3], al[ms][3]);
            }
#pragma unroll
            for (int j = 0; j < 4; ++j) {
                int base = j * 8 * 132 + kb;
                tfsplit(wfp[base],     bh[j][0], bl[j][0]);
                tfsplit(wfp[base + 4], bh[j][1], bl[j][1]);
            }
#pragma unroll
            for (int ms = 0; ms < 2; ++ms)
#pragma unroll
                for (int j = 0; j < 4; ++j) {
                    mma_tf32(c[ms][j], ah[ms][0], ah[ms][1], ah[ms][2], ah[ms][3],
                             bh[j][0], bh[j][1]);
                    mma_tf32(c[ms][j], al[ms][0], al[ms][1], al[ms][2], al[ms][3],
                             bh[j][0], bh[j][1]);
                    mma_tf32(c[ms][j], ah[ms][0], ah[ms][1], ah[ms][2], ah[ms][3],
                             bl[j][0], bl[j][1]);
                }
        }
        if (k < 4) {
            __syncthreads();
            fillW(k + 1);
            CP_COMMIT(); CP_WAIT0();
            __syncthreads();
        }
    }
    __syncthreads();

    float* convS = xf;
#pragma unroll
    for (int ms = 0; ms < 2; ++ms)
#pragma unroll
        for (int j = 0; j < 4; ++j) {
            int row = mw * 32 + ms * 16 + (lane >> 2);
            int col = nw * 32 + j * 8 + 2 * (lane & 3);
            convS[row * 68 + col]           = c[ms][j][0];
            convS[row * 68 + col + 1]       = c[ms][j][1];
            convS[(row + 8) * 68 + col]     = c[ms][j][2];
            convS[(row + 8) * 68 + col + 1] = c[ms][j][3];
        }
    __syncthreads();
    for (int idx = tid; idx < 42 * 64; idx += 256) {
        int oc = idx & 63, pl = idx >> 6;
        int p = bx * 42 + pl;
        if (p < L2P) {
            float sc = scS[oc], sh = shS[oc];
            float y0 = fmaf(convS[(3 * pl) * 68 + oc],     sc, sh);
            float y1 = fmaf(convS[(3 * pl + 1) * 68 + oc], sc, sh);
            float y2 = fmaf(convS[(3 * pl + 2) * 68 + oc], sc, sh);
            g_h2T[(b * L2P + p) * C2 + oc] = fmaxf(fmaxf(fmaxf(y0, y1), y2), 0.f);
        }
    }
}

// ============================================================
// Kernel 3: conv3 via mma.sync tf32 3x-split implicit GEMM
// ============================================================
#define CV3_SMEM ((131 * 68 + 192 * 68 + 128) * 4)   // 88,368 B

__global__ void __launch_bounds__(256, 2) k_conv3mma(
        const float* __restrict__ bias,
        const float* __restrict__ bng,
        const float* __restrict__ bnb,
        const float* __restrict__ bnm,
        const float* __restrict__ bnv) {
    extern __shared__ float sm[];
    float* xf  = sm;                       // [131][68]
    float* wf  = sm + 131 * 68;            // [192][68]
    float* scS = sm + 131 * 68 + 192 * 68; // [64]
    float* shS = scS + 64;

    const int b    = blockIdx.y;
    const int bx   = blockIdx.x;
    const int ct0  = bx * 126;
    const int tid  = threadIdx.x;
    const int lane = tid & 31;
    const int wid  = tid >> 5;
    const int mw   = wid & 3;
    const int nw   = wid >> 2;

    if (tid < 64) {
        float sc = bng[tid] * rsqrtf(bnv[tid] + EPS_BN);
        scS[tid] = sc;
        shS[tid] = bnb[tid] + (bias[tid] - bnm[tid]) * sc;
    }

    for (int idx = tid; idx < 131 * 16; idx += 256) {
        int j = idx >> 4, icq = idx & 15;
        int t = ct0 + j;
        float* dst = xf + j * 68 + icq * 4;
        if (t < L2P) cpa16(dst, &g_h2T[(b * L2P + t) * C2 + icq * 4]);
        else { dst[0] = 0.f; dst[1] = 0.f; dst[2] = 0.f; dst[3] = 0.f; }
    }
    for (int idx = tid; idx < 192 * 16; idx += 256) {
        int row = idx >> 4, icq = idx & 15;
        cpa16(wf + row * 68 + icq * 4, g_w3T + row * 64 + icq * 4);
    }
    CP_COMMIT(); CP_WAIT0();
    __syncthreads();

    float c[2][4][4];
#pragma unroll
    for (int ms = 0; ms < 2; ++ms)
#pragma unroll
        for (int j = 0; j < 4; ++j)
#pragma unroll
            for (int q = 0; q < 4; ++q) c[ms][j][q] = 0.f;

#pragma unroll 1
    for (int k = 0; k < 3; ++k) {
        const float* xfp = xf + (mw * 32 + (lane >> 2) + k) * 68 + (lane & 3);
        const float* wfp = wf + (k * 64 + nw * 32 + (lane >> 2)) * 68 + (lane & 3);
#pragma unroll 2
        for (int ks = 0; ks < 8; ++ks) {
            const int kb = ks * 8;
            unsigned ah[2][4], al[2][4], bh[4][2], bl[4][2];
#pragma unroll
            for (int ms = 0; ms < 2; ++ms) {
                int base = ms * 16 * 68 + kb;
                tfsplit(xfp[base],              ah[ms][0], al[ms][0]);
                tfsplit(xfp[base + 8 * 68],     ah[ms][1], al[ms][1]);
                tfsplit(xfp[base + 4],          ah[ms][2], al[ms][2]);
                tfsplit(xfp[base + 8 * 68 + 4], ah[ms][3], al[ms][3]);
            }
#pragma unroll
            for (int j = 0; j < 4; ++j) {
                int base = j * 8 * 68 + kb;
                tfsplit(wfp[base],     bh[j][0], bl[j][0]);
                tfsplit(wfp[base + 4], bh[j][1], bl[j][1]);
            }
#pragma unroll
            for (int ms = 0; ms < 2; ++ms)
#pragma unroll
                for (int j = 0; j < 4; ++j) {
                    mma_tf32(c[ms][j], ah[ms][0], ah[ms][1], ah[ms][2], ah[ms][3],
                             bh[j][0], bh[j][1]);
                    mma_tf32(c[ms][j], al[ms][0], al[ms][1], al[ms][2], al[ms][3],
                             bh[j][0], bh[j][1]);
                    mma_tf32(c[ms][j], ah[ms][0], ah[ms][1], ah[ms][2], ah[ms][3],
                             bl[j][0], bl[j][1]);
                }
        }
    }
    __syncthreads();

    float* convS = xf;   // [128][68]
#pragma unroll
    for (int ms = 0; ms < 2; ++ms)
#pragma unroll
        for (int j = 0; j < 4; ++j) {
            int row = mw * 32 + ms * 16 + (lane >> 2);
            int col = nw * 32 + j * 8 + 2 * (lane & 3);
            convS[row * 68 + col]           = c[ms][j][0];
            convS[row * 68 + col + 1]       = c[ms][j][1];
            convS[(row + 8) * 68 + col]     = c[ms][j][2];
            convS[(row + 8) * 68 + col + 1] = c[ms][j][3];
        }
    __syncthreads();
    for (int idx = tid; idx < 63 * 64; idx += 256) {
        int oc = idx & 63, pl = idx >> 6;
        int p = bx * 63 + pl;
        if (p < L3P) {
            float sc = scS[oc], sh = shS[oc];
            float y0 = fmaf(convS[(2 * pl) * 68 + oc],     sc, sh);
            float y1 = fmaf(convS[(2 * pl + 1) * 68 + oc], sc, sh);
            float y2 = fmaf(convS[(2 * pl + 2) * 68 + oc], sc, sh);
            float y = fmaxf(fmaxf(fmaxf(y0, y1), y2), 0.f);
            g_h3T[(oc * L3P + p) * BATCH + b] = y;
        }
    }
}

// ============================================================
// Kernel 4a: fc1 split-K, x-slab staged in smem.
// ============================================================
#define FCA_SMEM ((2016 + 10752) * 4)   // 51,072 B

__global__ void __launch_bounds__(256) k_fcA(const float* __restrict__ fc1w) {
    extern __shared__ float sm[];
    float* wsS = sm;           // [42][48]
    float* xS  = sm + 2016;    // [42][256]

    const int chunk = blockIdx.x;
    const int r = threadIdx.x;

    for (int idx = r; idx < 42 * 48; idx += 256) {
        int o = idx / 42, k = idx % 42;
        wsS[k * 48 + o] = fc1w[o * FCIN + chunk * 42 + k];
    }
    for (int i = r * 4; i < 10752; i += 1024)
        cpa16(xS + i, g_h3T + (size_t)chunk * 10752 + i);
    CP_COMMIT(); CP_WAIT0();
    __syncthreads();

    ull acc[24];
#pragma unroll
    for (int p = 0; p < 24; ++p) acc[p] = 0ull;

#pragma unroll 2
    for (int k = 0; k < 42; ++k) {
        ull xd = dup2(xS[k * 256 + r]);
#pragma unroll
        for (int p = 0; p < 24; ++p)
            fma2(acc[p], *(const ull*)&wsS[k * 48 + 2 * p], xd);
    }
    float* outp = &g_part[(chunk * BATCH + r) * 48];
#pragma unroll
    for (int p = 0; p < 24; ++p) {
        outp[2 * p]     = lo32(acc[p]);
        outp[2 * p + 1] = hi32(acc[p]);
    }
}

// ============================================================
// Kernel 4b: reduce (parallelized) + fc2/fc3/fc4 + tanh
// ============================================================
__global__ void __launch_bounds__(256) k_fcB(
        const float* __restrict__ fc1b,
        const float* __restrict__ fc2w, const float* __restrict__ fc2b,
        const float* __restrict__ fc3w, const float* __restrict__ fc3b,
        const float* __restrict__ fc4w, const float* __restrict__ fc4b) {
    const int r = blockIdx.x;
    const int tid = threadIdx.x;
    const int t = tid % 48, g = tid / 48;
    __shared__ float part[5][48];
    __shared__ float s1[48], s2[32], s3[16];

    if (g < 5) {
        int c0 = g * 52;
        int c1 = (c0 + 52 < 256) ? c0 + 52 : 256;
        float a = 0.f;
        for (int c = c0; c < c1; ++c)
            a += g_part[(c * BATCH + r) * 48 + t];
        part[g][t] = a;
    }
    __syncthreads();
    if (tid < 48) {
        float a = part[0][tid] + part[1][tid] + part[2][tid]
                + part[3][tid] + part[4][tid];
        s1[tid] = fmaxf(a + fc1b[tid], 0.f);
    }
    __syncthreads();
    if (tid < 32) {
        float a2 = 0.f;
#pragma unroll
        for (int k = 0; k < 48; ++k) a2 = fmaf(s1[k], fc2w[tid * 48 + k], a2);
        s2[tid] = fmaxf(a2 + fc2b[tid], 0.f);
    }
    __syncthreads();
    if (tid < 16) {
        float a3 = 0.f;
#pragma unroll
        for (int k = 0; k < 32; ++k) a3 = fmaf(s2[k], fc3w[tid * 32 + k], a3);
        s3[tid] = fmaxf(a3 + fc3b[tid], 0.f);
    }
    __syncthreads();
    if (tid < 5) {
        float a4 = 0.f;
#pragma unroll
        for (int k = 0; k < 16; ++k) a4 = fmaf(s3[k], fc4w[tid * 16 + k], a4);
        g_theta[r * 5 + tid] = tanhf(a4 + fc4b[tid]);
    }
}

// ============================================================
// Kernel 5: CPAB integrate + resample
// ============================================================
__global__ void k_warp(const float* __restrict__ x,
                       const float* __restrict__ basis,
                       float* __restrict__ out) {
    const int b   = blockIdx.x;
    const int tid = threadIdx.x;
    __shared__ float sa[6], sb[6];
    if (tid < 12) {
        float a = 0.f;
#pragma unroll
        for (int k = 0; k < 5; ++k)
            a = fmaf(g_theta[b * 5 + k], basis[tid * 5 + k], a);
        if (tid & 1) sb[tid >> 1] = a; else sa[tid >> 1] = a;
    }
    __syncthreads();
    float la[6], lb[6];
#pragma unroll
    for (int c = 0; c < 6; ++c) { la[c] = sa[c]; lb[c] = sb[c]; }
    const float INF = __int_as_float(0x7f800000);

    for (int r = 0; r < 8; ++r) {
        int i = tid + r * 256;
        float xv = (float)i / 2047.0f;
        float t = 1.0f;
#pragma unroll 1
        for (int it = 0; it < 7; ++it) {
            int c = (int)floorf(xv * 6.0f);
            c = c < 0 ? 0 : (c > 5 ? 5 : c);
            float a  = la[c];
            float bc = lb[c];
            float v  = fmaf(a, xv, bc);
            float xb = (v >= 0.f) ? (float)(c + 1) / 6.0f : (float)c / 6.0f;
            bool  big = fabsf(a) > 1e-8f;
            float a_s = big ? a : 1.0f;
            float boa = bc / a_s;
            float z   = xv + boa;
            float zb  = xb + boa;
            float zden  = (fabsf(z) > 1e-12f) ? z : 1e-12f;
            float ratio = zb / zden;
            float t_exp = logf(fmaxf(ratio, 1e-12f)) / a_s;
            float v_s   = (fabsf(v) > 1e-12f) ? v : 1.0f;
            float t_lin = (xb - xv) / v_s;
            float thit  = big ? t_exp : t_lin;
            bool valid = (fabsf(v) > 1e-12f) && (thit > 0.f) &&
                         ((big ? ratio : 1.0f) > 0.f);
            thit = valid ? thit : INF;
            float tau = fminf(t, thit);
            float x_new = big ? (z * expf(a * tau) - (z - xv))
                              : fmaf(bc, tau, xv);
            bool hit = (thit <= t);
            float nudge = (v >= 0.f) ? 1e-6f : -1e-6f;
            xv = hit ? (xb + nudge) : x_new;
            xv = fminf(fmaxf(xv, 0.f), 1.f);
            t = fmaxf(t - tau, 0.f);
        }
        float p = fminf(fmaxf(xv, 0.f), 1.f) * 2047.0f;
        int x0 = (int)floorf(p);
        x0 = x0 < 0 ? 0 : (x0 > 2046 ? 2046 : x0);
        float wgt = p - (float)x0;
#pragma unroll
        for (int ch = 0; ch < 3; ++ch) {
            float d0 = x[(b * 3 + ch) * SIGLEN + x0];
            float d1 = x[(b * 3 + ch) * SIGLEN + x0 + 1];
            out[(b * 3 + ch) * SIGLEN + i] = d0 * (1.0f - wgt) + d1 * wgt;
        }
    }
}

// ============================================================
extern "C" void kernel_launch(void* const* d_in, const int* in_sizes, int n_in,
                              void* d_out, int out_size) {
    const float* x     = (const float*)d_in[0];
    const float* c1w   = (const float*)d_in[1];
    const float* c1b   = (const float*)d_in[2];
    const float* bn1g  = (const float*)d_in[3];
    const float* bn1b  = (const float*)d_in[4];
    const float* bn1m  = (const float*)d_in[5];
    const float* bn1v  = (const float*)d_in[6];
    const float* c2w   = (const float*)d_in[7];
    const float* c2b   = (const float*)d_in[8];
    const float* bn2g  = (const float*)d_in[9];
    const float* bn2b  = (const float*)d_in[10];
    const float* bn2m  = (const float*)d_in[11];
    const float* bn2v  = (const float*)d_in[12];
    const float* c3w   = (const float*)d_in[13];
    const float* c3b   = (const float*)d_in[14];
    const float* bn3g  = (const float*)d_in[15];
    const float* bn3b  = (const float*)d_in[16];
    const float* bn3m  = (const float*)d_in[17];
    const float* bn3v  = (const float*)d_in[18];
    const float* fc1w  = (const float*)d_in[19];
    const float* fc1b  = (const float*)d_in[20];
    const float* fc2w  = (const float*)d_in[21];
    const float* fc2b  = (const float*)d_in[22];
    const float* fc3w  = (const float*)d_in[23];
    const float* fc3b  = (const float*)d_in[24];
    const float* fc4w  = (const float*)d_in[25];
    const float* fc4b  = (const float*)d_in[26];
    const float* basis = (const float*)d_in[27];
    float* out = (float*)d_out;

    static int attr_done = 0;
    if (!attr_done) {
        cudaFuncSetAttribute(k_conv2mma,
                             cudaFuncAttributeMaxDynamicSharedMemorySize, CV2_SMEM);
        cudaFuncSetAttribute(k_conv3mma,
                             cudaFuncAttributeMaxDynamicSharedMemorySize, CV3_SMEM);
        cudaFuncSetAttribute(k_fcA,
                             cudaFuncAttributeMaxDynamicSharedMemorySize, FCA_SMEM);
        attr_done = 1;
    }

    k_prep<<<160, 256>>>(c2w, c3w);
    dim3 g1(16, BATCH);  k_conv1<<<g1, 128>>>(x, c1w, c1b, bn1g, bn1b, bn1m, bn1v);
    dim3 g2(9,  BATCH);  k_conv2mma<<<g2, 256, CV2_SMEM>>>(c2b, bn2g, bn2b, bn2m, bn2v);
    dim3 g3(3,  BATCH);  k_conv3mma<<<g3, 256, CV3_SMEM>>>(c3b, bn3g, bn3b, bn3m, bn3v);
    k_fcA<<<256, 256, FCA_SMEM>>>(fc1w);
    k_fcB<<<BATCH, 256>>>(fc1b, fc2w, fc2b, fc3w, fc3b, fc4w, fc4b);
    k_warp<<<BATCH, 256>>>(x, basis, out);
}